// round 1
// baseline (speedup 1.0000x reference)
#include <cuda_runtime.h>
#include <math.h>

#define BATCH 1
#define NCAM 4
#define FCH 256
#define IH 45
#define IW 80
#define HW (IH*IW)          // 3600
#define DD 99
#define CC 128
#define KOUT (DD+CC)        // 227
#define NXV 100
#define NYV 100
#define NZV 5
#define NXY (NXV*NYV)       // 10000

// ---------------- scratch (static device globals; no allocs allowed) ----------
__device__ float g_x1[NCAM*FCH*HW];
__device__ float g_x2[NCAM*FCH*HW];
__device__ float g_logits[NCAM*KOUT*HW];
__device__ float g_mats[NCAM][24]; // [0:9) combine, [9:18) inv(post_rot), [18:21) post_trans, [21:24) cam2ego_trans

// ---------------- per-camera matrix prep ----------------
__device__ void inv3(const float* a, float* o) {
    float det = a[0]*(a[4]*a[8]-a[5]*a[7])
              - a[1]*(a[3]*a[8]-a[5]*a[6])
              + a[2]*(a[3]*a[7]-a[4]*a[6]);
    float id = 1.0f/det;
    o[0]=(a[4]*a[8]-a[5]*a[7])*id; o[1]=(a[2]*a[7]-a[1]*a[8])*id; o[2]=(a[1]*a[5]-a[2]*a[4])*id;
    o[3]=(a[5]*a[6]-a[3]*a[8])*id; o[4]=(a[0]*a[8]-a[2]*a[6])*id; o[5]=(a[2]*a[3]-a[0]*a[5])*id;
    o[6]=(a[3]*a[7]-a[4]*a[6])*id; o[7]=(a[1]*a[6]-a[0]*a[7])*id; o[8]=(a[0]*a[4]-a[1]*a[3])*id;
}

__global__ void prep_mats(const float* __restrict__ rot,
                          const float* __restrict__ ctrans,
                          const float* __restrict__ intr,
                          const float* __restrict__ prot,
                          const float* __restrict__ ptrans) {
    int n = threadIdx.x;
    if (n >= NCAM) return;
    float invK[9], invPR[9];
    inv3(intr + n*9, invK);
    inv3(prot + n*9, invPR);
    const float* R = rot + n*9;
    float* m = g_mats[n];
    #pragma unroll
    for (int i=0;i<3;i++)
        #pragma unroll
        for (int j=0;j<3;j++){
            float s=0.f;
            #pragma unroll
            for (int k=0;k<3;k++) s += R[i*3+k]*invK[k*3+j];
            m[i*3+j]=s;
        }
    #pragma unroll
    for (int i=0;i<9;i++) m[9+i]=invPR[i];
    #pragma unroll
    for (int i=0;i<3;i++){ m[18+i]=ptrans[n*3+i]; m[21+i]=ctrans[n*3+i]; }
}

// ---------------- 3x3 conv + BN + ReLU (implicit GEMM smem tiling) ----------------
// Block tile: 32 couts x (2 rows x 80 cols). 256 threads, each thread 4co x 5px.
#define CI_T 16
#define CO_T 32

__global__ __launch_bounds__(256)
void conv3x3_bn_relu(const float* __restrict__ in, const float* __restrict__ wgt,
                     const float* __restrict__ bias, const float* __restrict__ gam,
                     const float* __restrict__ bet, const float* __restrict__ mu,
                     const float* __restrict__ var, float* __restrict__ out)
{
    __shared__ float s_in[CI_T][4][84];   // rows h0-1..h0+2, cols -1..80 (82 used)
    __shared__ float s_w[CO_T][CI_T][9];

    int tid = threadIdx.x;
    int tx = tid & 15;          // 16 pixel groups of 5 along W
    int ty = (tid >> 4) & 1;    // 2 output rows
    int tz = tid >> 5;          // 8 cout groups of 4
    int h0 = blockIdx.x * 2;
    int cob = blockIdx.y * CO_T;
    int n  = blockIdx.z;
    const float* inb = in + (size_t)n*FCH*HW;

    float acc[4][5];
    #pragma unroll
    for (int a=0;a<4;a++)
        #pragma unroll
        for (int b=0;b<5;b++) acc[a][b]=0.f;

    for (int cc = 0; cc < FCH; cc += CI_T) {
        for (int idx = tid; idx < CI_T*4*82; idx += 256) {
            int ci  = idx / (4*82);
            int rem = idx % (4*82);
            int r = rem / 82;
            int c = rem % 82;
            int hh = h0 - 1 + r;
            int ww = c - 1;
            float val = 0.f;
            if (hh >= 0 && hh < IH && ww >= 0 && ww < IW)
                val = inb[(size_t)(cc+ci)*HW + hh*IW + ww];
            s_in[ci][r][c] = val;
        }
        for (int idx = tid; idx < CO_T*CI_T*9; idx += 256) {
            int co  = idx / (CI_T*9);
            int rem = idx % (CI_T*9);
            int ci = rem / 9;
            int k  = rem % 9;
            s_w[co][ci][k] = wgt[((size_t)(cob+co)*FCH + cc+ci)*9 + k];
        }
        __syncthreads();

        #pragma unroll 4
        for (int ci = 0; ci < CI_T; ci++) {
            #pragma unroll
            for (int ky = 0; ky < 3; ky++) {
                float vv[7];
                #pragma unroll
                for (int j = 0; j < 7; j++) vv[j] = s_in[ci][ty+ky][tx*5 + j];
                #pragma unroll
                for (int co = 0; co < 4; co++) {
                    float w0 = s_w[tz*4+co][ci][ky*3+0];
                    float w1 = s_w[tz*4+co][ci][ky*3+1];
                    float w2 = s_w[tz*4+co][ci][ky*3+2];
                    #pragma unroll
                    for (int p = 0; p < 5; p++)
                        acc[co][p] += vv[p]*w0 + vv[p+1]*w1 + vv[p+2]*w2;
                }
            }
        }
        __syncthreads();
    }

    int h = h0 + ty;
    if (h < IH) {
        #pragma unroll
        for (int co = 0; co < 4; co++) {
            int ch = cob + tz*4 + co;
            float scale = gam[ch] * rsqrtf(var[ch] + 1e-3f);
            float shift = bet[ch] - mu[ch]*scale;
            float bb = bias[ch];
            #pragma unroll
            for (int p = 0; p < 5; p++) {
                float y = (acc[co][p] + bb) * scale + shift;
                out[((size_t)n*FCH + ch)*HW + h*IW + tx*5 + p] = fmaxf(y, 0.f);
            }
        }
    }
}

// ---------------- 1x1 conv (227 out) ----------------
// Block tile: 32 k x 256 px; 256 threads, each 4k x 8px.
#define K1_T 32
#define PX_T 256
#define CI1_T 32

__global__ __launch_bounds__(256)
void conv1x1(const float* __restrict__ in, const float* __restrict__ wgt,
             const float* __restrict__ bias, float* __restrict__ out)
{
    __shared__ float s_x[CI1_T][PX_T];
    __shared__ float s_w[K1_T][CI1_T];
    int tid = threadIdx.x;
    int tp = tid & 31;       // 32 px groups of 8
    int tk = tid >> 5;       // 8 k groups of 4
    int p0 = blockIdx.x * PX_T;
    int kb = blockIdx.y * K1_T;
    int n  = blockIdx.z;
    const float* inb = in + (size_t)n*FCH*HW;

    float acc[4][8];
    #pragma unroll
    for (int a=0;a<4;a++)
        #pragma unroll
        for (int b=0;b<8;b++) acc[a][b]=0.f;

    for (int cc = 0; cc < FCH; cc += CI1_T) {
        for (int idx = tid; idx < CI1_T*PX_T; idx += 256) {
            int ci = idx / PX_T; int p = idx % PX_T;
            s_x[ci][p] = (p0+p < HW) ? inb[(size_t)(cc+ci)*HW + p0 + p] : 0.f;
        }
        for (int idx = tid; idx < K1_T*CI1_T; idx += 256) {
            int k = idx / CI1_T; int ci = idx % CI1_T;
            s_w[k][ci] = (kb+k < KOUT) ? wgt[(size_t)(kb+k)*FCH + cc+ci] : 0.f;
        }
        __syncthreads();
        #pragma unroll 8
        for (int ci = 0; ci < CI1_T; ci++) {
            float xv[8];
            #pragma unroll
            for (int j=0;j<8;j++) xv[j] = s_x[ci][tp*8+j];
            #pragma unroll
            for (int k=0;k<4;k++) {
                float wv = s_w[tk*4+k][ci];
                #pragma unroll
                for (int j=0;j<8;j++) acc[k][j] += wv*xv[j];
            }
        }
        __syncthreads();
    }
    #pragma unroll
    for (int k=0;k<4;k++) {
        int kk = kb + tk*4 + k;
        if (kk >= KOUT) continue;
        float bb = bias[kk];
        #pragma unroll
        for (int j=0;j<8;j++) {
            int p = p0 + tp*8 + j;
            if (p < HW) out[((size_t)n*KOUT + kk)*HW + p] = acc[k][j] + bb;
        }
    }
}

// ---------------- fused softmax + geometry + voxel scatter ----------------
// One block (128 threads) per ray (n,h,w). Threads = channels for scatter phase.
__global__ __launch_bounds__(128)
void scatter_kernel(const float* __restrict__ logits, float* __restrict__ out)
{
    __shared__ float s_p[DD];
    __shared__ int   s_vox[DD];
    __shared__ float s_red[128];

    int blk = blockIdx.x;
    int n   = blk / HW;
    int pix = blk % HW;
    int h = pix / IW, w = pix % IW;
    int t = threadIdx.x;
    const float* lg = logits + (size_t)n*KOUT*HW + pix;

    // softmax over D
    float x = (t < DD) ? lg[(size_t)t*HW] : -1e30f;
    s_red[t] = x; __syncthreads();
    #pragma unroll
    for (int s=64; s>0; s>>=1){ if (t<s) s_red[t]=fmaxf(s_red[t], s_red[t+s]); __syncthreads(); }
    float mx = s_red[0]; __syncthreads();
    float e = (t < DD) ? __expf(x - mx) : 0.f;
    s_red[t] = e; __syncthreads();
    #pragma unroll
    for (int s=64; s>0; s>>=1){ if (t<s) s_red[t]+=s_red[t+s]; __syncthreads(); }
    float inv = 1.f / s_red[0];
    if (t < DD) s_p[t] = e * inv;

    // geometry: per-depth voxel id (thread t = depth index)
    if (t < DD) {
        const float* m = g_mats[n];
        float dv = (float)(t+1);
        float fx = w * (639.0f/79.0f);
        float fy = h * (359.0f/44.0f);
        float q0 = fx - m[18], q1 = fy - m[19], q2 = dv - m[20];
        float r0 = m[ 9]*q0 + m[10]*q1 + m[11]*q2;
        float r1 = m[12]*q0 + m[13]*q1 + m[14]*q2;
        float r2 = m[15]*q0 + m[16]*q1 + m[17]*q2;
        float s0 = r0*r2, s1 = r1*r2, s2 = r2;
        float gx = m[0]*s0 + m[1]*s1 + m[2]*s2 + m[21];
        float gy = m[3]*s0 + m[4]*s1 + m[5]*s2 + m[22];
        float gz = m[6]*s0 + m[7]*s1 + m[8]*s2 + m[23];
        // vox = floor((g - (BXV - DX/2)) / DX); offsets: (0, -100, -10), inv DX: (.5,.5,.25)
        int vx = (int)floorf(gx * 0.5f);
        int vy = (int)floorf((gy + 100.f) * 0.5f);
        int vz = (int)floorf((gz + 10.f) * 0.25f);
        bool kept = (vx>=0 && vx<NXV && vy>=0 && vy<NYV && vz>=0 && vz<NZV);
        // out[((vz)*CC + c)*NXY + vx*NYV + vy] -> base independent of c:
        s_vox[t] = kept ? (vz*(CC*NXY) + vx*NYV + vy) : -1;
    }
    __syncthreads();

    // scatter: thread t = channel c; accumulate weight along same-voxel runs
    int c = t;
    float ctx = lg[(size_t)(DD + c)*HW];
    int cur = -1;
    float accw = 0.f;
    for (int d = 0; d < DD; d++) {
        int vb = s_vox[d];
        if (vb != cur) {
            if (cur >= 0) atomicAdd(out + cur + c*NXY, accw*ctx);
            cur = vb; accw = 0.f;
        }
        if (vb >= 0) accw += s_p[d];
    }
    if (cur >= 0) atomicAdd(out + cur + c*NXY, accw*ctx);
}

// ---------------- launcher ----------------
extern "C" void kernel_launch(void* const* d_in, const int* in_sizes, int n_in,
                              void* d_out, int out_size)
{
    const float* rot    = (const float*)d_in[0];
    const float* ctrans = (const float*)d_in[1];
    const float* intr   = (const float*)d_in[2];
    const float* prot   = (const float*)d_in[3];
    const float* ptrans = (const float*)d_in[4];
    const float* img    = (const float*)d_in[5];
    const float* w1 = (const float*)d_in[6];
    const float* b1 = (const float*)d_in[7];
    const float* g1 = (const float*)d_in[8];
    const float* be1= (const float*)d_in[9];
    const float* m1 = (const float*)d_in[10];
    const float* v1 = (const float*)d_in[11];
    const float* w2 = (const float*)d_in[12];
    const float* b2 = (const float*)d_in[13];
    const float* g2 = (const float*)d_in[14];
    const float* be2= (const float*)d_in[15];
    const float* m2 = (const float*)d_in[16];
    const float* v2 = (const float*)d_in[17];
    const float* w3 = (const float*)d_in[18];
    const float* b3 = (const float*)d_in[19];
    float* out = (float*)d_out;

    float *x1, *x2, *logits;
    cudaGetSymbolAddress((void**)&x1, g_x1);
    cudaGetSymbolAddress((void**)&x2, g_x2);
    cudaGetSymbolAddress((void**)&logits, g_logits);

    cudaMemsetAsync(out, 0, sizeof(float)*(size_t)out_size, 0);

    prep_mats<<<1, 32>>>(rot, ctrans, intr, prot, ptrans);

    dim3 cgrid((IH+1)/2, FCH/CO_T, NCAM);            // 23 x 8 x 4
    conv3x3_bn_relu<<<cgrid, 256>>>(img, w1, b1, g1, be1, m1, v1, x1);
    conv3x3_bn_relu<<<cgrid, 256>>>(x1,  w2, b2, g2, be2, m2, v2, x2);

    dim3 pgrid((HW+PX_T-1)/PX_T, (KOUT+K1_T-1)/K1_T, NCAM);  // 15 x 8 x 4
    conv1x1<<<pgrid, 256>>>(x2, w3, b3, logits);

    scatter_kernel<<<NCAM*HW, 128>>>(logits, out);
}

// round 5
// speedup vs baseline: 2.0459x; 2.0459x over previous
#include <cuda_runtime.h>
#include <cuda_bf16.h>
#include <cstdint>
#include <math.h>

#define NCAM 4
#define FCH 256
#define IH 45
#define IW 80
#define HWPX (IH*IW)            // 3600
#define NPX (NCAM*HWPX)         // 14400
#define DD 99
#define CC 128
#define NXV 100
#define NYV 100
#define NZV 5
#define NXY (NXV*NYV)

#define TILES_PER_CAM 29        // ceil(3600/128)
#define NTILES (TILES_PER_CAM*NCAM)
#define KCH 12                  // 768/64 chunks per tap

// ---------------- scratch ----------------
__device__ __nv_bfloat16 g_actA[(size_t)NPX*512];   // [px][hi 256 | lo 256]
__device__ __nv_bfloat16 g_actB[(size_t)NPX*512];
__device__ __nv_bfloat16 g_wp1[9*KCH*256*64];
__device__ __nv_bfloat16 g_wp2[9*KCH*256*64];
__device__ __nv_bfloat16 g_wp3[KCH*256*64];
__device__ float g_logits[(size_t)NPX*256];         // [px][227 used]
__device__ float g_ss[1280];                        // s1,t1,s2,t2,b3pad
__device__ float g_mats[NCAM][24];

// ---------------- helpers ----------------
__device__ __forceinline__ uint32_t smem_to_u32(const void* p) {
    uint32_t a;
    asm("{ .reg .u64 t; cvta.to.shared.u64 t, %1; cvt.u32.u64 %0, t; }" : "=r"(a) : "l"(p));
    return a;
}

__device__ __forceinline__ void cp_async16(uint32_t dst, const void* src, int sz) {
    asm volatile("cp.async.cg.shared.global [%0], [%1], 16, %2;"
                 :: "r"(dst), "l"(src), "r"(sz) : "memory");
}
__device__ __forceinline__ void cp_commit() {
    asm volatile("cp.async.commit_group;" ::: "memory");
}
__device__ __forceinline__ void cp_wait1() {
    asm volatile("cp.async.wait_group 1;" ::: "memory");
}
__device__ __forceinline__ void cp_wait0() {
    asm volatile("cp.async.wait_group 0;" ::: "memory");
}

__device__ __forceinline__ void ldmx4(uint32_t addr, uint32_t& r0, uint32_t& r1, uint32_t& r2, uint32_t& r3) {
    asm volatile("ldmatrix.sync.aligned.m8n8.x4.shared.b16 {%0,%1,%2,%3}, [%4];"
                 : "=r"(r0), "=r"(r1), "=r"(r2), "=r"(r3) : "r"(addr));
}

__device__ __forceinline__ void mma16816(float* d, const uint32_t* a, uint32_t b0, uint32_t b1) {
    asm volatile("mma.sync.aligned.m16n8k16.row.col.f32.bf16.bf16.f32 "
                 "{%0,%1,%2,%3}, {%4,%5,%6,%7}, {%8,%9}, {%0,%1,%2,%3};"
                 : "+f"(d[0]), "+f"(d[1]), "+f"(d[2]), "+f"(d[3])
                 : "r"(a[0]), "r"(a[1]), "r"(a[2]), "r"(a[3]), "r"(b0), "r"(b1));
}

// ---------------- smem layout for gemm kernel ----------------
// row stride 72 bf16 = 144 B (16B aligned; ldmatrix rows hit distinct banks)
#define RSTRIDE 144
#define OFF_SS   0                      // 512 floats = 2048 B
#define OFF_A0   2048
#define A_BYTES  (128*RSTRIDE)          // 18432
#define B_BYTES  (256*RSTRIDE)          // 36864
#define STAGE_BYTES (A_BYTES + B_BYTES) // 55296
#define SMEM_TOTAL (OFF_A0 + 2*STAGE_BYTES)  // 112640

// ---------------- GEMM conv kernel (mma.sync bf16, fp32 accum) ----------------
// Block: 512 threads = 16 warps (4x4). Block tile 128 px x 256 co.
// Warp tile 32 px x 64 co. K per tap = 768 (3-term hi/lo split), chunks of 64.
__global__ __launch_bounds__(512, 1)
void gemm_conv(const __nv_bfloat16* __restrict__ act_in,
               const __nv_bfloat16* __restrict__ wp,
               const float* __restrict__ ssA, const float* __restrict__ ssB,
               __nv_bfloat16* __restrict__ act_out,
               float* __restrict__ logits_out,
               int taps, int mode)   // mode 0: bn+relu+split out, 1: +bias -> logits
{
    extern __shared__ char smem[];
    uint32_t smem_base = smem_to_u32(smem);
    int tid = threadIdx.x;
    int wid = tid >> 5;
    int lane = tid & 31;

    int tile = blockIdx.x;
    int cam = tile / TILES_PER_CAM;
    int p0  = (tile % TILES_PER_CAM) * 128;

    // epilogue params
    {
        float* s_ss = (float*)smem;
        if (tid < 256) s_ss[tid] = ssA[tid];
        else           s_ss[tid] = ssB ? ssB[tid - 256] : 0.f;
    }

    const __nv_bfloat16* abase = act_in + (size_t)cam * HWPX * 512;
    int nch = taps * KCH;

    int warp_m = wid >> 2, warp_n = wid & 3;
    int m0 = warp_m * 32;
    int n0 = warp_n * 64;

    float acc[2][8][4];
    #pragma unroll
    for (int a = 0; a < 2; a++)
        #pragma unroll
        for (int b = 0; b < 8; b++)
            #pragma unroll
            for (int c = 0; c < 4; c++) acc[a][b][c] = 0.f;

    // A-load coords: 128 rows x 8 segs of 16B = 1024 -> 2 per thread
    int aseg = tid & 7;
    int ar0  = tid >> 3;           // rows 0..63
    int ar1  = ar0 + 64;           // rows 64..127
    int ap0  = p0 + ar0, ap1 = p0 + ar1;
    int ah0  = ap0 / IW, aw0 = ap0 % IW;
    int ah1  = ap1 / IW, aw1 = ap1 % IW;

    // issue loads for chunk k into given stage
    auto load_chunk = [&](int k, int stage) {
        uint32_t sa = smem_base + OFF_A0 + stage * STAGE_BYTES;
        uint32_t sb = sa + A_BYTES;
        int tap = k / KCH, kc = k % KCH;
        int dy = (taps == 9) ? (tap / 3 - 1) : 0;
        int dx = (taps == 9) ? (tap % 3 - 1) : 0;
        int sec = kc >> 2;
        int secoff = (sec == 1) ? 256 : 0;       // xhi, xlo, xhi
        int cbase = (kc & 3) * 64;
        // A: two rows per thread, seg = 16B of the 128B row
        {
            int h2 = ah0 + dy, w2 = aw0 + dx;
            bool ok = (ap0 < HWPX) && (h2 >= 0) && (h2 < IH) && (w2 >= 0) && (w2 < IW);
            const __nv_bfloat16* gp = ok
                ? (abase + (size_t)(h2 * IW + w2) * 512 + secoff + cbase + aseg * 8)
                : abase;
            cp_async16(sa + ar0 * RSTRIDE + aseg * 16, gp, ok ? 16 : 0);
        }
        {
            int h2 = ah1 + dy, w2 = aw1 + dx;
            bool ok = (ap1 < HWPX) && (h2 >= 0) && (h2 < IH) && (w2 >= 0) && (w2 < IW);
            const __nv_bfloat16* gp = ok
                ? (abase + (size_t)(h2 * IW + w2) * 512 + secoff + cbase + aseg * 8)
                : abase;
            cp_async16(sa + ar1 * RSTRIDE + aseg * 16, gp, ok ? 16 : 0);
        }
        // B: 256 rows x 8 segs = 2048 -> 4 per thread
        const __nv_bfloat16* wb = wp + (size_t)k * (256 * 64);
        #pragma unroll
        for (int i = 0; i < 4; i++) {
            int idx = tid + i * 512;
            int r = idx >> 3, seg = idx & 7;
            cp_async16(sb + r * RSTRIDE + seg * 16, wb + r * 64 + seg * 8, 16);
        }
        cp_commit();
    };

    load_chunk(0, 0);

    for (int k = 0; k < nch; k++) {
        if (k + 1 < nch) { load_chunk(k + 1, (k + 1) & 1); cp_wait1(); }
        else             { cp_wait0(); }
        __syncthreads();

        uint32_t sa = smem_base + OFF_A0 + (k & 1) * STAGE_BYTES;
        uint32_t sb = sa + A_BYTES;
        // per-lane ldmatrix base coords
        uint32_t a_row = m0 + (lane & 15);
        uint32_t a_coloff = (lane >> 4) * 16;            // bytes (8 bf16)
        uint32_t b_row = n0 + (lane >> 4) * 8 + (lane & 7);
        uint32_t b_coloff = ((lane >> 3) & 1) * 16;

        #pragma unroll
        for (int kk = 0; kk < 4; kk++) {
            uint32_t af[2][4];
            #pragma unroll
            for (int mf = 0; mf < 2; mf++) {
                uint32_t addr = sa + (a_row + mf * 16) * RSTRIDE + kk * 32 + a_coloff;
                ldmx4(addr, af[mf][0], af[mf][1], af[mf][2], af[mf][3]);
            }
            uint32_t bf[4][4];
            #pragma unroll
            for (int nf2 = 0; nf2 < 4; nf2++) {
                uint32_t addr = sb + (b_row + nf2 * 16) * RSTRIDE + kk * 32 + b_coloff;
                ldmx4(addr, bf[nf2][0], bf[nf2][1], bf[nf2][2], bf[nf2][3]);
            }
            #pragma unroll
            for (int mf = 0; mf < 2; mf++)
                #pragma unroll
                for (int nf = 0; nf < 8; nf++)
                    mma16816(acc[mf][nf], af[mf], bf[nf >> 1][(nf & 1) * 2], bf[nf >> 1][(nf & 1) * 2 + 1]);
        }
        __syncthreads();
    }

    // ---------------- epilogue ----------------
    const float* s_ss = (const float*)smem;
    int trow = lane >> 2;
    int tc   = (lane & 3) * 2;

    #pragma unroll
    for (int mf = 0; mf < 2; mf++) {
        #pragma unroll
        for (int half = 0; half < 2; half++) {
            int pr = m0 + mf * 16 + half * 8 + trow;
            int p = p0 + pr;
            if (p >= HWPX) continue;
            size_t pxg = (size_t)cam * HWPX + p;
            #pragma unroll
            for (int nf = 0; nf < 8; nf++) {
                int co = n0 + nf * 8 + tc;
                float d0 = acc[mf][nf][half * 2];
                float d1 = acc[mf][nf][half * 2 + 1];
                if (mode == 0) {
                    float y0 = fmaxf(d0 * s_ss[co]     + s_ss[256 + co],     0.f);
                    float y1 = fmaxf(d1 * s_ss[co + 1] + s_ss[256 + co + 1], 0.f);
                    __nv_bfloat162 hi2 = __floats2bfloat162_rn(y0, y1);
                    float l0f = y0 - __bfloat162float(__low2bfloat16(hi2));
                    float l1f = y1 - __bfloat162float(__high2bfloat16(hi2));
                    __nv_bfloat162 lo2 = __floats2bfloat162_rn(l0f, l1f);
                    __nv_bfloat16* outp = act_out + pxg * 512 + co;
                    *(__nv_bfloat162*)(outp)       = hi2;
                    *(__nv_bfloat162*)(outp + 256) = lo2;
                } else {
                    float2 v = make_float2(d0 + s_ss[co], d1 + s_ss[co + 1]);
                    *(float2*)(logits_out + pxg * 256 + co) = v;
                }
            }
        }
    }
}

// ---------------- input conversion: NCHW fp32 -> NHWC bf16 hi/lo ----------------
__global__ __launch_bounds__(256)
void convert_in(const float* __restrict__ img, __nv_bfloat16* __restrict__ out)
{
    __shared__ float s[64][65];
    int n = blockIdx.z;
    int ci0 = blockIdx.y * 64;
    int p0 = blockIdx.x * 64;
    int tid = threadIdx.x;
    for (int idx = tid; idx < 64 * 64; idx += 256) {
        int ci = idx / 64, p = idx % 64;
        float v = 0.f;
        if (p0 + p < HWPX) v = img[((size_t)(n * FCH + ci0 + ci)) * HWPX + p0 + p];
        s[ci][p] = v;
    }
    __syncthreads();
    for (int idx = tid; idx < 64 * 64; idx += 256) {
        int p = idx / 64, ci = idx % 64;
        if (p0 + p >= HWPX) continue;
        float v = s[ci][p];
        __nv_bfloat16 hi = __float2bfloat16(v);
        __nv_bfloat16 lo = __float2bfloat16(v - __bfloat162float(hi));
        size_t base = ((size_t)n * HWPX + p0 + p) * 512 + ci0 + ci;
        out[base] = hi;
        out[base + 256] = lo;
    }
}

// ---------------- weight prep ----------------
__global__ void prep_w3x3(const float* __restrict__ w, __nv_bfloat16* __restrict__ wp)
{
    int idx = blockIdx.x * 256 + threadIdx.x;
    if (idx >= 9 * KCH * 256 * 64) return;
    int j   = idx & 63;
    int co  = (idx >> 6) & 255;
    int kc  = (idx >> 14) % KCH;
    int tap = idx / (KCH * 16384);
    int k = kc * 64 + j;
    int sec = k >> 8;
    int ci = k - sec * 256;
    int ky = tap / 3, kx = tap % 3;
    float v = w[(((size_t)co * 256 + ci) * 3 + ky) * 3 + kx];
    __nv_bfloat16 hi = __float2bfloat16(v);
    wp[idx] = (sec < 2) ? hi : __float2bfloat16(v - __bfloat162float(hi));
}

__global__ void prep_w1x1(const float* __restrict__ w, __nv_bfloat16* __restrict__ wp)
{
    int idx = blockIdx.x * 256 + threadIdx.x;
    if (idx >= KCH * 256 * 64) return;
    int j  = idx & 63;
    int co = (idx >> 6) & 255;
    int kc = idx >> 14;
    int k = kc * 64 + j;
    int sec = k >> 8;
    int ci = k - sec * 256;
    float v = (co < 227) ? w[(size_t)co * 256 + ci] : 0.f;
    __nv_bfloat16 hi = __float2bfloat16(v);
    wp[idx] = (sec < 2) ? hi : __float2bfloat16(v - __bfloat162float(hi));
}

__global__ void prep_ss(const float* b1, const float* g1, const float* be1, const float* m1, const float* v1,
                        const float* b2, const float* g2, const float* be2, const float* m2, const float* v2,
                        const float* b3)
{
    int c = threadIdx.x;
    float s1 = g1[c] * rsqrtf(v1[c] + 1e-3f);
    g_ss[c] = s1;
    g_ss[256 + c] = be1[c] + (b1[c] - m1[c]) * s1;
    float s2 = g2[c] * rsqrtf(v2[c] + 1e-3f);
    g_ss[512 + c] = s2;
    g_ss[768 + c] = be2[c] + (b2[c] - m2[c]) * s2;
    g_ss[1024 + c] = (c < 227) ? b3[c] : 0.f;
}

// ---------------- per-camera matrices ----------------
__device__ void inv3(const float* a, float* o) {
    float det = a[0]*(a[4]*a[8]-a[5]*a[7]) - a[1]*(a[3]*a[8]-a[5]*a[6]) + a[2]*(a[3]*a[7]-a[4]*a[6]);
    float id = 1.0f/det;
    o[0]=(a[4]*a[8]-a[5]*a[7])*id; o[1]=(a[2]*a[7]-a[1]*a[8])*id; o[2]=(a[1]*a[5]-a[2]*a[4])*id;
    o[3]=(a[5]*a[6]-a[3]*a[8])*id; o[4]=(a[0]*a[8]-a[2]*a[6])*id; o[5]=(a[2]*a[3]-a[0]*a[5])*id;
    o[6]=(a[3]*a[7]-a[4]*a[6])*id; o[7]=(a[1]*a[6]-a[0]*a[7])*id; o[8]=(a[0]*a[4]-a[1]*a[3])*id;
}

__global__ void prep_mats(const float* __restrict__ rot, const float* __restrict__ ctrans,
                          const float* __restrict__ intr, const float* __restrict__ prot,
                          const float* __restrict__ ptrans) {
    int n = threadIdx.x;
    if (n >= NCAM) return;
    float invK[9], invPR[9];
    inv3(intr + n*9, invK);
    inv3(prot + n*9, invPR);
    const float* R = rot + n*9;
    float* m = g_mats[n];
    #pragma unroll
    for (int i=0;i<3;i++)
        #pragma unroll
        for (int j=0;j<3;j++){
            float s=0.f;
            #pragma unroll
            for (int k2=0;k2<3;k2++) s += R[i*3+k2]*invK[k2*3+j];
            m[i*3+j]=s;
        }
    #pragma unroll
    for (int i=0;i<9;i++) m[9+i]=invPR[i];
    #pragma unroll
    for (int i=0;i<3;i++){ m[18+i]=ptrans[n*3+i]; m[21+i]=ctrans[n*3+i]; }
}

// ---------------- fused softmax + geometry + voxel scatter ----------------
__global__ __launch_bounds__(128)
void scatter_kernel(const float* __restrict__ logits, float* __restrict__ out)
{
    __shared__ float s_p[DD];
    __shared__ int   s_vox[DD];
    __shared__ float s_red[128];

    int blk = blockIdx.x;
    int n   = blk / HWPX;
    int pix = blk % HWPX;
    int h = pix / IW, w = pix % IW;
    int t = threadIdx.x;
    const float* lg = logits + ((size_t)n * HWPX + pix) * 256;

    float x = (t < DD) ? lg[t] : -1e30f;
    s_red[t] = x; __syncthreads();
    #pragma unroll
    for (int s=64; s>0; s>>=1){ if (t<s) s_red[t]=fmaxf(s_red[t], s_red[t+s]); __syncthreads(); }
    float mx = s_red[0]; __syncthreads();
    float e = (t < DD) ? __expf(x - mx) : 0.f;
    s_red[t] = e; __syncthreads();
    #pragma unroll
    for (int s=64; s>0; s>>=1){ if (t<s) s_red[t]+=s_red[t+s]; __syncthreads(); }
    float inv = 1.f / s_red[0];
    if (t < DD) s_p[t] = e * inv;

    if (t < DD) {
        const float* m = g_mats[n];
        float dv = (float)(t+1);
        float fx = w * (639.0f/79.0f);
        float fy = h * (359.0f/44.0f);
        float q0 = fx - m[18], q1 = fy - m[19], q2 = dv - m[20];
        float r0 = m[ 9]*q0 + m[10]*q1 + m[11]*q2;
        float r1 = m[12]*q0 + m[13]*q1 + m[14]*q2;
        float r2 = m[15]*q0 + m[16]*q1 + m[17]*q2;
        float s0 = r0*r2, s1 = r1*r2, s2 = r2;
        float gx = m[0]*s0 + m[1]*s1 + m[2]*s2 + m[21];
        float gy = m[3]*s0 + m[4]*s1 + m[5]*s2 + m[22];
        float gz = m[6]*s0 + m[7]*s1 + m[8]*s2 + m[23];
        int vx = (int)floorf(gx * 0.5f);
        int vy = (int)floorf((gy + 100.f) * 0.5f);
        int vz = (int)floorf((gz + 10.f) * 0.25f);
        bool kept = (vx>=0 && vx<NXV && vy>=0 && vy<NYV && vz>=0 && vz<NZV);
        s_vox[t] = kept ? (vz*(CC*NXY) + vx*NYV + vy) : -1;
    }
    __syncthreads();

    int c = t;
    float ctx = lg[DD + c];
    int cur = -1;
    float accw = 0.f;
    for (int d = 0; d < DD; d++) {
        int vb = s_vox[d];
        if (vb != cur) {
            if (cur >= 0) atomicAdd(out + cur + c*NXY, accw*ctx);
            cur = vb; accw = 0.f;
        }
        if (vb >= 0) accw += s_p[d];
    }
    if (cur >= 0) atomicAdd(out + cur + c*NXY, accw*ctx);
}

// ---------------- launcher ----------------
extern "C" void kernel_launch(void* const* d_in, const int* in_sizes, int n_in,
                              void* d_out, int out_size)
{
    const float* rot    = (const float*)d_in[0];
    const float* ctrans = (const float*)d_in[1];
    const float* intr   = (const float*)d_in[2];
    const float* prot   = (const float*)d_in[3];
    const float* ptrans = (const float*)d_in[4];
    const float* img    = (const float*)d_in[5];
    const float* w1 = (const float*)d_in[6];
    const float* b1 = (const float*)d_in[7];
    const float* g1 = (const float*)d_in[8];
    const float* be1= (const float*)d_in[9];
    const float* m1 = (const float*)d_in[10];
    const float* v1 = (const float*)d_in[11];
    const float* w2 = (const float*)d_in[12];
    const float* b2 = (const float*)d_in[13];
    const float* g2 = (const float*)d_in[14];
    const float* be2= (const float*)d_in[15];
    const float* m2 = (const float*)d_in[16];
    const float* v2 = (const float*)d_in[17];
    const float* w3 = (const float*)d_in[18];
    const float* b3 = (const float*)d_in[19];
    float* out = (float*)d_out;

    __nv_bfloat16 *actA, *actB, *wp1, *wp2, *wp3;
    float *logits, *ss;
    cudaGetSymbolAddress((void**)&actA, g_actA);
    cudaGetSymbolAddress((void**)&actB, g_actB);
    cudaGetSymbolAddress((void**)&wp1, g_wp1);
    cudaGetSymbolAddress((void**)&wp2, g_wp2);
    cudaGetSymbolAddress((void**)&wp3, g_wp3);
    cudaGetSymbolAddress((void**)&logits, g_logits);
    cudaGetSymbolAddress((void**)&ss, g_ss);

    cudaFuncSetAttribute(gemm_conv, cudaFuncAttributeMaxDynamicSharedMemorySize, SMEM_TOTAL);

    cudaMemsetAsync(out, 0, sizeof(float)*(size_t)out_size, 0);

    prep_mats<<<1, 32>>>(rot, ctrans, intr, prot, ptrans);
    prep_ss<<<1, 256>>>(b1,g1,be1,m1,v1, b2,g2,be2,m2,v2, b3);

    dim3 cvgrid((HWPX + 63)/64, FCH/64, NCAM);
    convert_in<<<cvgrid, 256>>>(img, actA);

    prep_w3x3<<<(9*KCH*256*64)/256, 256>>>(w1, wp1);
    prep_w3x3<<<(9*KCH*256*64)/256, 256>>>(w2, wp2);
    prep_w1x1<<<(KCH*256*64)/256, 256>>>(w3, wp3);

    gemm_conv<<<NTILES, 512, SMEM_TOTAL>>>(actA, wp1, ss,        ss + 256, actB, nullptr, 9, 0);
    gemm_conv<<<NTILES, 512, SMEM_TOTAL>>>(actB, wp2, ss + 512,  ss + 768, actA, nullptr, 9, 0);
    gemm_conv<<<NTILES, 512, SMEM_TOTAL>>>(actA, wp3, ss + 1024, nullptr,  nullptr, logits, 1, 1);

    scatter_kernel<<<NPX, 128>>>(logits, out);
}

// round 7
// speedup vs baseline: 3.1754x; 1.5521x over previous
#include <cuda_runtime.h>
#include <cuda_bf16.h>
#include <cstdint>
#include <math.h>

#define NCAM 4
#define FCH 256
#define IH 45
#define IW 80
#define HWPX (IH*IW)            // 3600
#define NPX (NCAM*HWPX)         // 14400
#define DD 99
#define CC 128
#define NXV 100
#define NYV 100
#define NZV 5
#define NXY (NXV*NYV)

#define TILES_PER_CAM 29        // ceil(3600/128)
#define NTILES (TILES_PER_CAM*NCAM)
#define KCH 12                  // 768/64 chunks per tap

// ---------------- scratch ----------------
__device__ __nv_bfloat16 g_actA[(size_t)NPX*512];   // [px][hi 256 | lo 256]
__device__ __nv_bfloat16 g_actB[(size_t)NPX*512];
__device__ __nv_bfloat16 g_wp1[9*KCH*256*64];
__device__ __nv_bfloat16 g_wp2[9*KCH*256*64];
__device__ __nv_bfloat16 g_wp3[KCH*256*64];
__device__ float g_logits[(size_t)NPX*256];         // [px][227 used]
__device__ float g_ss[1280];                        // s1,t1,s2,t2,b3pad
__device__ float g_mats[NCAM][24];
__device__ __align__(16) float g_scratch[(size_t)NZV*NXY*CC];  // channel-contiguous BEV

// ---------------- helpers ----------------
__device__ __forceinline__ uint32_t smem_to_u32(const void* p) {
    uint32_t a;
    asm("{ .reg .u64 t; cvta.to.shared.u64 t, %1; cvt.u32.u64 %0, t; }" : "=r"(a) : "l"(p));
    return a;
}

__device__ __forceinline__ void cp_async16(uint32_t dst, const void* src, int sz) {
    asm volatile("cp.async.cg.shared.global [%0], [%1], 16, %2;"
                 :: "r"(dst), "l"(src), "r"(sz) : "memory");
}
__device__ __forceinline__ void cp_commit() {
    asm volatile("cp.async.commit_group;" ::: "memory");
}
__device__ __forceinline__ void cp_wait1() {
    asm volatile("cp.async.wait_group 1;" ::: "memory");
}
__device__ __forceinline__ void cp_wait0() {
    asm volatile("cp.async.wait_group 0;" ::: "memory");
}

__device__ __forceinline__ void ldmx4(uint32_t addr, uint32_t& r0, uint32_t& r1, uint32_t& r2, uint32_t& r3) {
    asm volatile("ldmatrix.sync.aligned.m8n8.x4.shared.b16 {%0,%1,%2,%3}, [%4];"
                 : "=r"(r0), "=r"(r1), "=r"(r2), "=r"(r3) : "r"(addr));
}

__device__ __forceinline__ void mma16816(float* d, const uint32_t* a, uint32_t b0, uint32_t b1) {
    asm volatile("mma.sync.aligned.m16n8k16.row.col.f32.bf16.bf16.f32 "
                 "{%0,%1,%2,%3}, {%4,%5,%6,%7}, {%8,%9}, {%0,%1,%2,%3};"
                 : "+f"(d[0]), "+f"(d[1]), "+f"(d[2]), "+f"(d[3])
                 : "r"(a[0]), "r"(a[1]), "r"(a[2]), "r"(a[3]), "r"(b0), "r"(b1));
}

// ---------------- smem layout for gemm kernel ----------------
#define RSTRIDE 144
#define OFF_SS   0                      // 512 floats = 2048 B
#define OFF_A0   2048
#define A_BYTES  (128*RSTRIDE)          // 18432
#define B_BYTES  (256*RSTRIDE)          // 36864
#define STAGE_BYTES (A_BYTES + B_BYTES) // 55296
#define SMEM_TOTAL (OFF_A0 + 2*STAGE_BYTES)  // 112640

// ---------------- GEMM conv kernel (mma.sync bf16, fp32 accum) ----------------
__global__ __launch_bounds__(512, 1)
void gemm_conv(const __nv_bfloat16* __restrict__ act_in,
               const __nv_bfloat16* __restrict__ wp,
               const float* __restrict__ ssA, const float* __restrict__ ssB,
               __nv_bfloat16* __restrict__ act_out,
               float* __restrict__ logits_out,
               int taps, int mode)
{
    extern __shared__ char smem[];
    uint32_t smem_base = smem_to_u32(smem);
    int tid = threadIdx.x;
    int wid = tid >> 5;
    int lane = tid & 31;

    int tile = blockIdx.x;
    int cam = tile / TILES_PER_CAM;
    int p0  = (tile % TILES_PER_CAM) * 128;

    {
        float* s_ss = (float*)smem;
        if (tid < 256) s_ss[tid] = ssA[tid];
        else           s_ss[tid] = ssB ? ssB[tid - 256] : 0.f;
    }

    const __nv_bfloat16* abase = act_in + (size_t)cam * HWPX * 512;
    int nch = taps * KCH;

    int warp_m = wid >> 2, warp_n = wid & 3;
    int m0 = warp_m * 32;
    int n0 = warp_n * 64;

    float acc[2][8][4];
    #pragma unroll
    for (int a = 0; a < 2; a++)
        #pragma unroll
        for (int b = 0; b < 8; b++)
            #pragma unroll
            for (int c = 0; c < 4; c++) acc[a][b][c] = 0.f;

    int aseg = tid & 7;
    int ar0  = tid >> 3;
    int ar1  = ar0 + 64;
    int ap0  = p0 + ar0, ap1 = p0 + ar1;
    int ah0  = ap0 / IW, aw0 = ap0 % IW;
    int ah1  = ap1 / IW, aw1 = ap1 % IW;

    auto load_chunk = [&](int k, int stage) {
        uint32_t sa = smem_base + OFF_A0 + stage * STAGE_BYTES;
        uint32_t sb = sa + A_BYTES;
        int tap = k / KCH, kc = k % KCH;
        int dy = (taps == 9) ? (tap / 3 - 1) : 0;
        int dx = (taps == 9) ? (tap % 3 - 1) : 0;
        int sec = kc >> 2;
        int secoff = (sec == 1) ? 256 : 0;
        int cbase = (kc & 3) * 64;
        {
            int h2 = ah0 + dy, w2 = aw0 + dx;
            bool ok = (ap0 < HWPX) && (h2 >= 0) && (h2 < IH) && (w2 >= 0) && (w2 < IW);
            const __nv_bfloat16* gp = ok
                ? (abase + (size_t)(h2 * IW + w2) * 512 + secoff + cbase + aseg * 8)
                : abase;
            cp_async16(sa + ar0 * RSTRIDE + aseg * 16, gp, ok ? 16 : 0);
        }
        {
            int h2 = ah1 + dy, w2 = aw1 + dx;
            bool ok = (ap1 < HWPX) && (h2 >= 0) && (h2 < IH) && (w2 >= 0) && (w2 < IW);
            const __nv_bfloat16* gp = ok
                ? (abase + (size_t)(h2 * IW + w2) * 512 + secoff + cbase + aseg * 8)
                : abase;
            cp_async16(sa + ar1 * RSTRIDE + aseg * 16, gp, ok ? 16 : 0);
        }
        const __nv_bfloat16* wb = wp + (size_t)k * (256 * 64);
        #pragma unroll
        for (int i = 0; i < 4; i++) {
            int idx = tid + i * 512;
            int r = idx >> 3, seg = idx & 7;
            cp_async16(sb + r * RSTRIDE + seg * 16, wb + r * 64 + seg * 8, 16);
        }
        cp_commit();
    };

    load_chunk(0, 0);

    for (int k = 0; k < nch; k++) {
        if (k + 1 < nch) { load_chunk(k + 1, (k + 1) & 1); cp_wait1(); }
        else             { cp_wait0(); }
        __syncthreads();

        uint32_t sa = smem_base + OFF_A0 + (k & 1) * STAGE_BYTES;
        uint32_t sb = sa + A_BYTES;
        uint32_t a_row = m0 + (lane & 15);
        uint32_t a_coloff = (lane >> 4) * 16;
        uint32_t b_row = n0 + (lane >> 4) * 8 + (lane & 7);
        uint32_t b_coloff = ((lane >> 3) & 1) * 16;

        #pragma unroll
        for (int kk = 0; kk < 4; kk++) {
            uint32_t af[2][4];
            #pragma unroll
            for (int mf = 0; mf < 2; mf++) {
                uint32_t addr = sa + (a_row + mf * 16) * RSTRIDE + kk * 32 + a_coloff;
                ldmx4(addr, af[mf][0], af[mf][1], af[mf][2], af[mf][3]);
            }
            uint32_t bf[4][4];
            #pragma unroll
            for (int nf2 = 0; nf2 < 4; nf2++) {
                uint32_t addr = sb + (b_row + nf2 * 16) * RSTRIDE + kk * 32 + b_coloff;
                ldmx4(addr, bf[nf2][0], bf[nf2][1], bf[nf2][2], bf[nf2][3]);
            }
            #pragma unroll
            for (int mf = 0; mf < 2; mf++)
                #pragma unroll
                for (int nf = 0; nf < 8; nf++)
                    mma16816(acc[mf][nf], af[mf], bf[nf >> 1][(nf & 1) * 2], bf[nf >> 1][(nf & 1) * 2 + 1]);
        }
        __syncthreads();
    }

    const float* s_ss = (const float*)smem;
    int trow = lane >> 2;
    int tc   = (lane & 3) * 2;

    #pragma unroll
    for (int mf = 0; mf < 2; mf++) {
        #pragma unroll
        for (int half = 0; half < 2; half++) {
            int pr = m0 + mf * 16 + half * 8 + trow;
            int p = p0 + pr;
            if (p >= HWPX) continue;
            size_t pxg = (size_t)cam * HWPX + p;
            #pragma unroll
            for (int nf = 0; nf < 8; nf++) {
                int co = n0 + nf * 8 + tc;
                float d0 = acc[mf][nf][half * 2];
                float d1 = acc[mf][nf][half * 2 + 1];
                if (mode == 0) {
                    float y0 = fmaxf(d0 * s_ss[co]     + s_ss[256 + co],     0.f);
                    float y1 = fmaxf(d1 * s_ss[co + 1] + s_ss[256 + co + 1], 0.f);
                    __nv_bfloat162 hi2 = __floats2bfloat162_rn(y0, y1);
                    float l0f = y0 - __bfloat162float(__low2bfloat16(hi2));
                    float l1f = y1 - __bfloat162float(__high2bfloat16(hi2));
                    __nv_bfloat162 lo2 = __floats2bfloat162_rn(l0f, l1f);
                    __nv_bfloat16* outp = act_out + pxg * 512 + co;
                    *(__nv_bfloat162*)(outp)       = hi2;
                    *(__nv_bfloat162*)(outp + 256) = lo2;
                } else {
                    float2 v = make_float2(d0 + s_ss[co], d1 + s_ss[co + 1]);
                    *(float2*)(logits_out + pxg * 256 + co) = v;
                }
            }
        }
    }
}

// ---------------- input conversion: NCHW fp32 -> NHWC bf16 hi/lo ----------------
__global__ __launch_bounds__(256)
void convert_in(const float* __restrict__ img, __nv_bfloat16* __restrict__ out)
{
    __shared__ float s[64][65];
    int n = blockIdx.z;
    int ci0 = blockIdx.y * 64;
    int p0 = blockIdx.x * 64;
    int tid = threadIdx.x;
    for (int idx = tid; idx < 64 * 64; idx += 256) {
        int ci = idx / 64, p = idx % 64;
        float v = 0.f;
        if (p0 + p < HWPX) v = img[((size_t)(n * FCH + ci0 + ci)) * HWPX + p0 + p];
        s[ci][p] = v;
    }
    __syncthreads();
    for (int idx = tid; idx < 64 * 64; idx += 256) {
        int p = idx / 64, ci = idx % 64;
        if (p0 + p >= HWPX) continue;
        float v = s[ci][p];
        __nv_bfloat16 hi = __float2bfloat16(v);
        __nv_bfloat16 lo = __float2bfloat16(v - __bfloat162float(hi));
        size_t base = ((size_t)n * HWPX + p0 + p) * 512 + ci0 + ci;
        out[base] = hi;
        out[base + 256] = lo;
    }
}

// ---------------- weight prep ----------------
__global__ void prep_w3x3(const float* __restrict__ w, __nv_bfloat16* __restrict__ wp)
{
    int idx = blockIdx.x * 256 + threadIdx.x;
    if (idx >= 9 * KCH * 256 * 64) return;
    int j   = idx & 63;
    int co  = (idx >> 6) & 255;
    int kc  = (idx >> 14) % KCH;
    int tap = idx / (KCH * 16384);
    int k = kc * 64 + j;
    int sec = k >> 8;
    int ci = k - sec * 256;
    int ky = tap / 3, kx = tap % 3;
    float v = w[(((size_t)co * 256 + ci) * 3 + ky) * 3 + kx];
    __nv_bfloat16 hi = __float2bfloat16(v);
    wp[idx] = (sec < 2) ? hi : __float2bfloat16(v - __bfloat162float(hi));
}

__global__ void prep_w1x1(const float* __restrict__ w, __nv_bfloat16* __restrict__ wp)
{
    int idx = blockIdx.x * 256 + threadIdx.x;
    if (idx >= KCH * 256 * 64) return;
    int j  = idx & 63;
    int co = (idx >> 6) & 255;
    int kc = idx >> 14;
    int k = kc * 64 + j;
    int sec = k >> 8;
    int ci = k - sec * 256;
    float v = (co < 227) ? w[(size_t)co * 256 + ci] : 0.f;
    __nv_bfloat16 hi = __float2bfloat16(v);
    wp[idx] = (sec < 2) ? hi : __float2bfloat16(v - __bfloat162float(hi));
}

__global__ void prep_ss(const float* b1, const float* g1, const float* be1, const float* m1, const float* v1,
                        const float* b2, const float* g2, const float* be2, const float* m2, const float* v2,
                        const float* b3)
{
    int c = threadIdx.x;
    float s1 = g1[c] * rsqrtf(v1[c] + 1e-3f);
    g_ss[c] = s1;
    g_ss[256 + c] = be1[c] + (b1[c] - m1[c]) * s1;
    float s2 = g2[c] * rsqrtf(v2[c] + 1e-3f);
    g_ss[512 + c] = s2;
    g_ss[768 + c] = be2[c] + (b2[c] - m2[c]) * s2;
    g_ss[1024 + c] = (c < 227) ? b3[c] : 0.f;
}

// ---------------- per-camera matrices ----------------
__device__ void inv3(const float* a, float* o) {
    float det = a[0]*(a[4]*a[8]-a[5]*a[7]) - a[1]*(a[3]*a[8]-a[5]*a[6]) + a[2]*(a[3]*a[7]-a[4]*a[6]);
    float id = 1.0f/det;
    o[0]=(a[4]*a[8]-a[5]*a[7])*id; o[1]=(a[2]*a[7]-a[1]*a[8])*id; o[2]=(a[1]*a[5]-a[2]*a[4])*id;
    o[3]=(a[5]*a[6]-a[3]*a[8])*id; o[4]=(a[0]*a[8]-a[2]*a[6])*id; o[5]=(a[2]*a[3]-a[0]*a[5])*id;
    o[6]=(a[3]*a[7]-a[4]*a[6])*id; o[7]=(a[1]*a[6]-a[0]*a[7])*id; o[8]=(a[0]*a[4]-a[1]*a[3])*id;
}

__global__ void prep_mats(const float* __restrict__ rot, const float* __restrict__ ctrans,
                          const float* __restrict__ intr, const float* __restrict__ prot,
                          const float* __restrict__ ptrans) {
    int n = threadIdx.x;
    if (n >= NCAM) return;
    float invK[9], invPR[9];
    inv3(intr + n*9, invK);
    inv3(prot + n*9, invPR);
    const float* R = rot + n*9;
    float* m = g_mats[n];
    #pragma unroll
    for (int i=0;i<3;i++)
        #pragma unroll
        for (int j=0;j<3;j++){
            float s=0.f;
            #pragma unroll
            for (int k2=0;k2<3;k2++) s += R[i*3+k2]*invK[k2*3+j];
            m[i*3+j]=s;
        }
    #pragma unroll
    for (int i=0;i<9;i++) m[9+i]=invPR[i];
    #pragma unroll
    for (int i=0;i<3;i++){ m[18+i]=ptrans[n*3+i]; m[21+i]=ctrans[n*3+i]; }
}

// ---------------- fused softmax + geometry + run-compressed scatter ----------------
// Scatters into channel-contiguous scratch [vz][vx][vy][c] via red.global.add.v4.f32
__global__ __launch_bounds__(128)
void scatter_kernel(const float* __restrict__ logits, float* __restrict__ scratch)
{
    __shared__ float s_p[DD];
    __shared__ int   s_vox[DD];
    __shared__ float s_red[128];
    __shared__ __align__(16) float s_ctx[CC];
    __shared__ int   s_woff[4];
    __shared__ int   s_runstart[DD];
    __shared__ int   s_runvb[DD];
    __shared__ float s_runw[DD];
    __shared__ int   s_nruns;

    int blk = blockIdx.x;
    int n   = blk / HWPX;
    int pix = blk % HWPX;
    int h = pix / IW, w = pix % IW;
    int t = threadIdx.x;
    int lane = t & 31, warp = t >> 5;
    const float* lg = logits + ((size_t)n * HWPX + pix) * 256;

    // context channels (coalesced)
    s_ctx[t] = lg[DD + t];

    // softmax over D
    float x = (t < DD) ? lg[t] : -1e30f;
    s_red[t] = x; __syncthreads();
    #pragma unroll
    for (int s=64; s>0; s>>=1){ if (t<s) s_red[t]=fmaxf(s_red[t], s_red[t+s]); __syncthreads(); }
    float mx = s_red[0]; __syncthreads();
    float e = (t < DD) ? __expf(x - mx) : 0.f;
    s_red[t] = e; __syncthreads();
    #pragma unroll
    for (int s=64; s>0; s>>=1){ if (t<s) s_red[t]+=s_red[t+s]; __syncthreads(); }
    float inv = 1.f / s_red[0];
    if (t < DD) s_p[t] = e * inv;

    // geometry -> channel-contiguous voxel base (vz*NXY + vx*NYV + vy), -1 if dropped
    if (t < DD) {
        const float* m = g_mats[n];
        float dv = (float)(t+1);
        float fx = w * (639.0f/79.0f);
        float fy = h * (359.0f/44.0f);
        float q0 = fx - m[18], q1 = fy - m[19], q2 = dv - m[20];
        float r0 = m[ 9]*q0 + m[10]*q1 + m[11]*q2;
        float r1 = m[12]*q0 + m[13]*q1 + m[14]*q2;
        float r2 = m[15]*q0 + m[16]*q1 + m[17]*q2;
        float s0 = r0*r2, s1 = r1*r2, s2 = r2;
        float gx = m[0]*s0 + m[1]*s1 + m[2]*s2 + m[21];
        float gy = m[3]*s0 + m[4]*s1 + m[5]*s2 + m[22];
        float gz = m[6]*s0 + m[7]*s1 + m[8]*s2 + m[23];
        int vx = (int)floorf(gx * 0.5f);
        int vy = (int)floorf((gy + 100.f) * 0.5f);
        int vz = (int)floorf((gz + 10.f) * 0.25f);
        bool kept = (vx>=0 && vx<NXV && vy>=0 && vy<NYV && vz>=0 && vz<NZV);
        s_vox[t] = kept ? (vz*NXY + vx*NYV + vy) : -1;
    }
    __syncthreads();

    // run detection + ballot prefix scan
    int f = 0;
    if (t < DD) f = (t == 0) || (s_vox[t] != s_vox[t-1]);
    unsigned bal = __ballot_sync(0xffffffffu, f);
    int wpre = __popc(bal & ((1u << lane) - 1));
    if (lane == 0) s_woff[warp] = __popc(bal);
    __syncthreads();
    if (t == 0) {
        int a = 0;
        #pragma unroll
        for (int wv = 0; wv < 4; wv++) { int v = s_woff[wv]; s_woff[wv] = a; a += v; }
        s_nruns = a;
    }
    __syncthreads();
    if (f) s_runstart[s_woff[warp] + wpre] = t;
    __syncthreads();
    int nruns = s_nruns;
    if (t < nruns) {
        int st = s_runstart[t];
        int en = (t + 1 < nruns) ? s_runstart[t+1] : DD;
        float wsum = 0.f;
        for (int d = st; d < en; d++) wsum += s_p[d];
        s_runvb[t] = s_vox[st];
        s_runw[t]  = wsum;
    }
    __syncthreads();

    // flush: 4 runs in parallel (one per warp), 32 lanes x v4 = 128 channels
    const float4* ctx4 = (const float4*)s_ctx;
    float4 cv = ctx4[lane];
    for (int r = warp; r < nruns; r += 4) {
        int vb = s_runvb[r];
        if (vb < 0) continue;
        float wv = s_runw[r];
        float* ptr = scratch + (size_t)vb * CC + lane * 4;
        asm volatile("red.global.add.v4.f32 [%0], {%1,%2,%3,%4};"
                     :: "l"(ptr), "f"(wv*cv.x), "f"(wv*cv.y), "f"(wv*cv.z), "f"(wv*cv.w)
                     : "memory");
    }
}

// ---------------- scratch [vz][xy][c] -> out [vz][c][xy] ----------------
__global__ __launch_bounds__(256)
void bev_transpose(const float* __restrict__ scratch, float* __restrict__ out)
{
    __shared__ float s[32][129];
    int vz = blockIdx.y;
    int xy0 = blockIdx.x * 32;
    int tid = threadIdx.x;
    #pragma unroll
    for (int i = 0; i < 16; i++) {
        int idx = tid + i * 256;
        int c = idx & 127, xyl = idx >> 7;
        int xy = xy0 + xyl;
        s[xyl][c] = (xy < NXY) ? scratch[((size_t)vz * NXY + xy) * CC + c] : 0.f;
    }
    __syncthreads();
    #pragma unroll
    for (int i = 0; i < 16; i++) {
        int idx = tid + i * 256;
        int xyl = idx & 31, c = idx >> 5;
        int xy = xy0 + xyl;
        if (xy < NXY) out[((size_t)vz * CC + c) * NXY + xy] = s[xyl][c];
    }
}

// ---------------- launcher ----------------
extern "C" void kernel_launch(void* const* d_in, const int* in_sizes, int n_in,
                              void* d_out, int out_size)
{
    const float* rot    = (const float*)d_in[0];
    const float* ctrans = (const float*)d_in[1];
    const float* intr   = (const float*)d_in[2];
    const float* prot   = (const float*)d_in[3];
    const float* ptrans = (const float*)d_in[4];
    const float* img    = (const float*)d_in[5];
    const float* w1 = (const float*)d_in[6];
    const float* b1 = (const float*)d_in[7];
    const float* g1 = (const float*)d_in[8];
    const float* be1= (const float*)d_in[9];
    const float* m1 = (const float*)d_in[10];
    const float* v1 = (const float*)d_in[11];
    const float* w2 = (const float*)d_in[12];
    const float* b2 = (const float*)d_in[13];
    const float* g2 = (const float*)d_in[14];
    const float* be2= (const float*)d_in[15];
    const float* m2 = (const float*)d_in[16];
    const float* v2 = (const float*)d_in[17];
    const float* w3 = (const float*)d_in[18];
    const float* b3 = (const float*)d_in[19];
    float* out = (float*)d_out;

    __nv_bfloat16 *actA, *actB, *wp1, *wp2, *wp3;
    float *logits, *ss, *scratch;
    cudaGetSymbolAddress((void**)&actA, g_actA);
    cudaGetSymbolAddress((void**)&actB, g_actB);
    cudaGetSymbolAddress((void**)&wp1, g_wp1);
    cudaGetSymbolAddress((void**)&wp2, g_wp2);
    cudaGetSymbolAddress((void**)&wp3, g_wp3);
    cudaGetSymbolAddress((void**)&logits, g_logits);
    cudaGetSymbolAddress((void**)&ss, g_ss);
    cudaGetSymbolAddress((void**)&scratch, g_scratch);

    cudaFuncSetAttribute(gemm_conv, cudaFuncAttributeMaxDynamicSharedMemorySize, SMEM_TOTAL);

    cudaMemsetAsync(scratch, 0, sizeof(float)*(size_t)NZV*NXY*CC, 0);

    prep_mats<<<1, 32>>>(rot, ctrans, intr, prot, ptrans);
    prep_ss<<<1, 256>>>(b1,g1,be1,m1,v1, b2,g2,be2,m2,v2, b3);

    dim3 cvgrid((HWPX + 63)/64, FCH/64, NCAM);
    convert_in<<<cvgrid, 256>>>(img, actA);

    prep_w3x3<<<(9*KCH*256*64)/256, 256>>>(w1, wp1);
    prep_w3x3<<<(9*KCH*256*64)/256, 256>>>(w2, wp2);
    prep_w1x1<<<(KCH*256*64)/256, 256>>>(w3, wp3);

    gemm_conv<<<NTILES, 512, SMEM_TOTAL>>>(actA, wp1, ss,        ss + 256, actB, nullptr, 9, 0);
    gemm_conv<<<NTILES, 512, SMEM_TOTAL>>>(actB, wp2, ss + 512,  ss + 768, actA, nullptr, 9, 0);
    gemm_conv<<<NTILES, 512, SMEM_TOTAL>>>(actA, wp3, ss + 1024, nullptr,  nullptr, logits, 1, 1);

    scatter_kernel<<<NPX, 128>>>(logits, scratch);

    bev_transpose<<<dim3((NXY + 31)/32, NZV), 256>>>(scratch, out);
}

// round 8
// speedup vs baseline: 4.1587x; 1.3097x over previous
#include <cuda_runtime.h>
#include <cuda_fp16.h>
#include <cstdint>
#include <math.h>

#define NCAM 4
#define FCH 256
#define IH 45
#define IW 80
#define HWPX (IH*IW)            // 3600
#define NPX (NCAM*HWPX)         // 14400
#define DD 99
#define CC 128
#define NXV 100
#define NYV 100
#define NZV 5
#define NXY (NXV*NYV)

#define TILES_PER_CAM 29        // ceil(3600/128)
#define NTILES (TILES_PER_CAM*NCAM)
#define KCH 8                   // 512/64 chunks per tap (fp16 2-term split)

// ---------------- scratch ----------------
__device__ __half g_actA[(size_t)NPX*512];   // [px][hi 256 | lo 256]
__device__ __half g_actB[(size_t)NPX*512];
__device__ __half g_wp1[9*KCH*256*64];
__device__ __half g_wp2[9*KCH*256*64];
__device__ __half g_wp3[KCH*256*64];
__device__ float g_logits[(size_t)NPX*256];         // [px][227 used]
__device__ float g_ss[1280];                        // s1,t1,s2,t2,b3pad
__device__ float g_mats[NCAM][24];
__device__ __align__(16) float g_scratch[(size_t)NZV*NXY*CC];  // channel-contiguous BEV

// ---------------- helpers ----------------
__device__ __forceinline__ uint32_t smem_to_u32(const void* p) {
    uint32_t a;
    asm("{ .reg .u64 t; cvta.to.shared.u64 t, %1; cvt.u32.u64 %0, t; }" : "=r"(a) : "l"(p));
    return a;
}

__device__ __forceinline__ void cp_async16(uint32_t dst, const void* src, int sz) {
    asm volatile("cp.async.cg.shared.global [%0], [%1], 16, %2;"
                 :: "r"(dst), "l"(src), "r"(sz) : "memory");
}
__device__ __forceinline__ void cp_commit() {
    asm volatile("cp.async.commit_group;" ::: "memory");
}
__device__ __forceinline__ void cp_wait1() {
    asm volatile("cp.async.wait_group 1;" ::: "memory");
}
__device__ __forceinline__ void cp_wait0() {
    asm volatile("cp.async.wait_group 0;" ::: "memory");
}

__device__ __forceinline__ void ldmx4(uint32_t addr, uint32_t& r0, uint32_t& r1, uint32_t& r2, uint32_t& r3) {
    asm volatile("ldmatrix.sync.aligned.m8n8.x4.shared.b16 {%0,%1,%2,%3}, [%4];"
                 : "=r"(r0), "=r"(r1), "=r"(r2), "=r"(r3) : "r"(addr));
}

__device__ __forceinline__ void mma16816(float* d, const uint32_t* a, uint32_t b0, uint32_t b1) {
    asm volatile("mma.sync.aligned.m16n8k16.row.col.f32.f16.f16.f32 "
                 "{%0,%1,%2,%3}, {%4,%5,%6,%7}, {%8,%9}, {%0,%1,%2,%3};"
                 : "+f"(d[0]), "+f"(d[1]), "+f"(d[2]), "+f"(d[3])
                 : "r"(a[0]), "r"(a[1]), "r"(a[2]), "r"(a[3]), "r"(b0), "r"(b1));
}

// ---------------- smem layout for gemm kernel ----------------
#define RSTRIDE 144
#define OFF_SS   0                      // 512 floats = 2048 B
#define OFF_A0   2048
#define A_BYTES  (128*RSTRIDE)          // 18432
#define B_BYTES  (256*RSTRIDE)          // 36864
#define STAGE_BYTES (A_BYTES + B_BYTES) // 55296
#define SMEM_TOTAL (OFF_A0 + 2*STAGE_BYTES)  // 112640

// ---------------- GEMM conv kernel (mma.sync fp16, fp32 accum) ----------------
__global__ __launch_bounds__(512, 1)
void gemm_conv(const __half* __restrict__ act_in,
               const __half* __restrict__ wp,
               const float* __restrict__ ssA, const float* __restrict__ ssB,
               __half* __restrict__ act_out,
               float* __restrict__ logits_out,
               int taps, int mode)
{
    extern __shared__ char smem[];
    uint32_t smem_base = smem_to_u32(smem);
    int tid = threadIdx.x;
    int wid = tid >> 5;
    int lane = tid & 31;

    int tile = blockIdx.x;
    int cam = tile / TILES_PER_CAM;
    int p0  = (tile % TILES_PER_CAM) * 128;

    {
        float* s_ss = (float*)smem;
        if (tid < 256) s_ss[tid] = ssA[tid];
        else           s_ss[tid] = ssB ? ssB[tid - 256] : 0.f;
    }

    const __half* abase = act_in + (size_t)cam * HWPX * 512;
    int nch = taps * KCH;

    int warp_m = wid >> 2, warp_n = wid & 3;
    int m0 = warp_m * 32;
    int n0 = warp_n * 64;

    float acc[2][8][4];
    #pragma unroll
    for (int a = 0; a < 2; a++)
        #pragma unroll
        for (int b = 0; b < 8; b++)
            #pragma unroll
            for (int c = 0; c < 4; c++) acc[a][b][c] = 0.f;

    int aseg = tid & 7;
    int ar0  = tid >> 3;
    int ar1  = ar0 + 64;
    int ap0  = p0 + ar0, ap1 = p0 + ar1;
    int ah0  = ap0 / IW, aw0 = ap0 % IW;
    int ah1  = ap1 / IW, aw1 = ap1 % IW;

    auto load_chunk = [&](int k, int stage) {
        uint32_t sa = smem_base + OFF_A0 + stage * STAGE_BYTES;
        uint32_t sb = sa + A_BYTES;
        int tap = k / KCH, kc = k % KCH;
        int dy = (taps == 9) ? (tap / 3 - 1) : 0;
        int dx = (taps == 9) ? (tap % 3 - 1) : 0;
        int secoff = (kc >> 2) * 256;          // xhi | xlo
        int cbase = (kc & 3) * 64;
        {
            int h2 = ah0 + dy, w2 = aw0 + dx;
            bool ok = (ap0 < HWPX) && (h2 >= 0) && (h2 < IH) && (w2 >= 0) && (w2 < IW);
            const __half* gp = ok
                ? (abase + (size_t)(h2 * IW + w2) * 512 + secoff + cbase + aseg * 8)
                : abase;
            cp_async16(sa + ar0 * RSTRIDE + aseg * 16, gp, ok ? 16 : 0);
        }
        {
            int h2 = ah1 + dy, w2 = aw1 + dx;
            bool ok = (ap1 < HWPX) && (h2 >= 0) && (h2 < IH) && (w2 >= 0) && (w2 < IW);
            const __half* gp = ok
                ? (abase + (size_t)(h2 * IW + w2) * 512 + secoff + cbase + aseg * 8)
                : abase;
            cp_async16(sa + ar1 * RSTRIDE + aseg * 16, gp, ok ? 16 : 0);
        }
        const __half* wb = wp + (size_t)k * (256 * 64);
        #pragma unroll
        for (int i = 0; i < 4; i++) {
            int idx = tid + i * 512;
            int r = idx >> 3, seg = idx & 7;
            cp_async16(sb + r * RSTRIDE + seg * 16, wb + r * 64 + seg * 8, 16);
        }
        cp_commit();
    };

    load_chunk(0, 0);

    for (int k = 0; k < nch; k++) {
        if (k + 1 < nch) { load_chunk(k + 1, (k + 1) & 1); cp_wait1(); }
        else             { cp_wait0(); }
        __syncthreads();

        uint32_t sa = smem_base + OFF_A0 + (k & 1) * STAGE_BYTES;
        uint32_t sb = sa + A_BYTES;
        uint32_t a_row = m0 + (lane & 15);
        uint32_t a_coloff = (lane >> 4) * 16;
        uint32_t b_row = n0 + (lane >> 4) * 8 + (lane & 7);
        uint32_t b_coloff = ((lane >> 3) & 1) * 16;

        #pragma unroll
        for (int kk = 0; kk < 4; kk++) {
            uint32_t af[2][4];
            #pragma unroll
            for (int mf = 0; mf < 2; mf++) {
                uint32_t addr = sa + (a_row + mf * 16) * RSTRIDE + kk * 32 + a_coloff;
                ldmx4(addr, af[mf][0], af[mf][1], af[mf][2], af[mf][3]);
            }
            uint32_t bf[4][4];
            #pragma unroll
            for (int nf2 = 0; nf2 < 4; nf2++) {
                uint32_t addr = sb + (b_row + nf2 * 16) * RSTRIDE + kk * 32 + b_coloff;
                ldmx4(addr, bf[nf2][0], bf[nf2][1], bf[nf2][2], bf[nf2][3]);
            }
            #pragma unroll
            for (int mf = 0; mf < 2; mf++)
                #pragma unroll
                for (int nf = 0; nf < 8; nf++)
                    mma16816(acc[mf][nf], af[mf], bf[nf >> 1][(nf & 1) * 2], bf[nf >> 1][(nf & 1) * 2 + 1]);
        }
        __syncthreads();
    }

    const float* s_ss = (const float*)smem;
    int trow = lane >> 2;
    int tc   = (lane & 3) * 2;

    #pragma unroll
    for (int mf = 0; mf < 2; mf++) {
        #pragma unroll
        for (int half2i = 0; half2i < 2; half2i++) {
            int pr = m0 + mf * 16 + half2i * 8 + trow;
            int p = p0 + pr;
            if (p >= HWPX) continue;
            size_t pxg = (size_t)cam * HWPX + p;
            #pragma unroll
            for (int nf = 0; nf < 8; nf++) {
                int co = n0 + nf * 8 + tc;
                float d0 = acc[mf][nf][half2i * 2];
                float d1 = acc[mf][nf][half2i * 2 + 1];
                if (mode == 0) {
                    float y0 = fmaxf(d0 * s_ss[co]     + s_ss[256 + co],     0.f);
                    float y1 = fmaxf(d1 * s_ss[co + 1] + s_ss[256 + co + 1], 0.f);
                    __half h0 = __float2half_rn(y0);
                    __half h1 = __float2half_rn(y1);
                    __half l0 = __float2half_rn(y0 - __half2float(h0));
                    __half l1 = __float2half_rn(y1 - __half2float(h1));
                    __half* outp = act_out + pxg * 512 + co;
                    *(__half2*)(outp)       = __halves2half2(h0, h1);
                    *(__half2*)(outp + 256) = __halves2half2(l0, l1);
                } else {
                    float2 v = make_float2(d0 + s_ss[co], d1 + s_ss[co + 1]);
                    *(float2*)(logits_out + pxg * 256 + co) = v;
                }
            }
        }
    }
}

// ---------------- input conversion: NCHW fp32 -> NHWC fp16 hi/lo ----------------
__global__ __launch_bounds__(256)
void convert_in(const float* __restrict__ img, __half* __restrict__ out)
{
    __shared__ float s[64][65];
    int n = blockIdx.z;
    int ci0 = blockIdx.y * 64;
    int p0 = blockIdx.x * 64;
    int tid = threadIdx.x;
    for (int idx = tid; idx < 64 * 64; idx += 256) {
        int ci = idx / 64, p = idx % 64;
        float v = 0.f;
        if (p0 + p < HWPX) v = img[((size_t)(n * FCH + ci0 + ci)) * HWPX + p0 + p];
        s[ci][p] = v;
    }
    __syncthreads();
    for (int idx = tid; idx < 64 * 64; idx += 256) {
        int p = idx / 64, ci = idx % 64;
        if (p0 + p >= HWPX) continue;
        float v = s[ci][p];
        __half hi = __float2half_rn(v);
        __half lo = __float2half_rn(v - __half2float(hi));
        size_t base = ((size_t)n * HWPX + p0 + p) * 512 + ci0 + ci;
        out[base] = hi;
        out[base + 256] = lo;
    }
}

// ---------------- weight prep (single fp16, duplicated across both A sections) ----
__global__ void prep_w3x3(const float* __restrict__ w, __half* __restrict__ wp)
{
    int idx = blockIdx.x * 256 + threadIdx.x;
    if (idx >= 9 * KCH * 256 * 64) return;
    int j   = idx & 63;
    int co  = (idx >> 6) & 255;
    int kc  = (idx >> 14) % KCH;
    int tap = idx / (KCH * 16384);
    int k = kc * 64 + j;
    int ci = k & 255;
    int ky = tap / 3, kx = tap % 3;
    float v = w[(((size_t)co * 256 + ci) * 3 + ky) * 3 + kx];
    wp[idx] = __float2half_rn(v);
}

__global__ void prep_w1x1(const float* __restrict__ w, __half* __restrict__ wp)
{
    int idx = blockIdx.x * 256 + threadIdx.x;
    if (idx >= KCH * 256 * 64) return;
    int j  = idx & 63;
    int co = (idx >> 6) & 255;
    int kc = idx >> 14;
    int k = kc * 64 + j;
    int ci = k & 255;
    float v = (co < 227) ? w[(size_t)co * 256 + ci] : 0.f;
    wp[idx] = __float2half_rn(v);
}

__global__ void prep_ss(const float* b1, const float* g1, const float* be1, const float* m1, const float* v1,
                        const float* b2, const float* g2, const float* be2, const float* m2, const float* v2,
                        const float* b3)
{
    int c = threadIdx.x;
    float s1 = g1[c] * rsqrtf(v1[c] + 1e-3f);
    g_ss[c] = s1;
    g_ss[256 + c] = be1[c] + (b1[c] - m1[c]) * s1;
    float s2 = g2[c] * rsqrtf(v2[c] + 1e-3f);
    g_ss[512 + c] = s2;
    g_ss[768 + c] = be2[c] + (b2[c] - m2[c]) * s2;
    g_ss[1024 + c] = (c < 227) ? b3[c] : 0.f;
}

// ---------------- per-camera matrices ----------------
__device__ void inv3(const float* a, float* o) {
    float det = a[0]*(a[4]*a[8]-a[5]*a[7]) - a[1]*(a[3]*a[8]-a[5]*a[6]) + a[2]*(a[3]*a[7]-a[4]*a[6]);
    float id = 1.0f/det;
    o[0]=(a[4]*a[8]-a[5]*a[7])*id; o[1]=(a[2]*a[7]-a[1]*a[8])*id; o[2]=(a[1]*a[5]-a[2]*a[4])*id;
    o[3]=(a[5]*a[6]-a[3]*a[8])*id; o[4]=(a[0]*a[8]-a[2]*a[6])*id; o[5]=(a[2]*a[3]-a[0]*a[5])*id;
    o[6]=(a[3]*a[7]-a[4]*a[6])*id; o[7]=(a[1]*a[6]-a[0]*a[7])*id; o[8]=(a[0]*a[4]-a[1]*a[3])*id;
}

__global__ void prep_mats(const float* __restrict__ rot, const float* __restrict__ ctrans,
                          const float* __restrict__ intr, const float* __restrict__ prot,
                          const float* __restrict__ ptrans) {
    int n = threadIdx.x;
    if (n >= NCAM) return;
    float invK[9], invPR[9];
    inv3(intr + n*9, invK);
    inv3(prot + n*9, invPR);
    const float* R = rot + n*9;
    float* m = g_mats[n];
    #pragma unroll
    for (int i=0;i<3;i++)
        #pragma unroll
        for (int j=0;j<3;j++){
            float s=0.f;
            #pragma unroll
            for (int k2=0;k2<3;k2++) s += R[i*3+k2]*invK[k2*3+j];
            m[i*3+j]=s;
        }
    #pragma unroll
    for (int i=0;i<9;i++) m[9+i]=invPR[i];
    #pragma unroll
    for (int i=0;i<3;i++){ m[18+i]=ptrans[n*3+i]; m[21+i]=ctrans[n*3+i]; }
}

// ---------------- fused softmax + geometry + run-compressed scatter ----------------
__global__ __launch_bounds__(128)
void scatter_kernel(const float* __restrict__ logits, float* __restrict__ scratch)
{
    __shared__ float s_p[DD];
    __shared__ int   s_vox[DD];
    __shared__ float s_red[128];
    __shared__ __align__(16) float s_ctx[CC];
    __shared__ int   s_woff[4];
    __shared__ int   s_runstart[DD];
    __shared__ int   s_runvb[DD];
    __shared__ float s_runw[DD];
    __shared__ int   s_nruns;

    int blk = blockIdx.x;
    int n   = blk / HWPX;
    int pix = blk % HWPX;
    int h = pix / IW, w = pix % IW;
    int t = threadIdx.x;
    int lane = t & 31, warp = t >> 5;
    const float* lg = logits + ((size_t)n * HWPX + pix) * 256;

    s_ctx[t] = lg[DD + t];

    float x = (t < DD) ? lg[t] : -1e30f;
    s_red[t] = x; __syncthreads();
    #pragma unroll
    for (int s=64; s>0; s>>=1){ if (t<s) s_red[t]=fmaxf(s_red[t], s_red[t+s]); __syncthreads(); }
    float mx = s_red[0]; __syncthreads();
    float e = (t < DD) ? __expf(x - mx) : 0.f;
    s_red[t] = e; __syncthreads();
    #pragma unroll
    for (int s=64; s>0; s>>=1){ if (t<s) s_red[t]+=s_red[t+s]; __syncthreads(); }
    float inv = 1.f / s_red[0];
    if (t < DD) s_p[t] = e * inv;

    if (t < DD) {
        const float* m = g_mats[n];
        float dv = (float)(t+1);
        float fx = w * (639.0f/79.0f);
        float fy = h * (359.0f/44.0f);
        float q0 = fx - m[18], q1 = fy - m[19], q2 = dv - m[20];
        float r0 = m[ 9]*q0 + m[10]*q1 + m[11]*q2;
        float r1 = m[12]*q0 + m[13]*q1 + m[14]*q2;
        float r2 = m[15]*q0 + m[16]*q1 + m[17]*q2;
        float s0 = r0*r2, s1 = r1*r2, s2 = r2;
        float gx = m[0]*s0 + m[1]*s1 + m[2]*s2 + m[21];
        float gy = m[3]*s0 + m[4]*s1 + m[5]*s2 + m[22];
        float gz = m[6]*s0 + m[7]*s1 + m[8]*s2 + m[23];
        int vx = (int)floorf(gx * 0.5f);
        int vy = (int)floorf((gy + 100.f) * 0.5f);
        int vz = (int)floorf((gz + 10.f) * 0.25f);
        bool kept = (vx>=0 && vx<NXV && vy>=0 && vy<NYV && vz>=0 && vz<NZV);
        s_vox[t] = kept ? (vz*NXY + vx*NYV + vy) : -1;
    }
    __syncthreads();

    int f = 0;
    if (t < DD) f = (t == 0) || (s_vox[t] != s_vox[t-1]);
    unsigned bal = __ballot_sync(0xffffffffu, f);
    int wpre = __popc(bal & ((1u << lane) - 1));
    if (lane == 0) s_woff[warp] = __popc(bal);
    __syncthreads();
    if (t == 0) {
        int a = 0;
        #pragma unroll
        for (int wv = 0; wv < 4; wv++) { int v = s_woff[wv]; s_woff[wv] = a; a += v; }
        s_nruns = a;
    }
    __syncthreads();
    if (f) s_runstart[s_woff[warp] + wpre] = t;
    __syncthreads();
    int nruns = s_nruns;
    if (t < nruns) {
        int st = s_runstart[t];
        int en = (t + 1 < nruns) ? s_runstart[t+1] : DD;
        float wsum = 0.f;
        for (int d = st; d < en; d++) wsum += s_p[d];
        s_runvb[t] = s_vox[st];
        s_runw[t]  = wsum;
    }
    __syncthreads();

    const float4* ctx4 = (const float4*)s_ctx;
    float4 cv = ctx4[lane];
    for (int r = warp; r < nruns; r += 4) {
        int vb = s_runvb[r];
        if (vb < 0) continue;
        float wv = s_runw[r];
        float* ptr = scratch + (size_t)vb * CC + lane * 4;
        asm volatile("red.global.add.v4.f32 [%0], {%1,%2,%3,%4};"
                     :: "l"(ptr), "f"(wv*cv.x), "f"(wv*cv.y), "f"(wv*cv.z), "f"(wv*cv.w)
                     : "memory");
    }
}

// ---------------- scratch [vz][xy][c] -> out [vz][c][xy] ----------------
__global__ __launch_bounds__(256)
void bev_transpose(const float* __restrict__ scratch, float* __restrict__ out)
{
    __shared__ float s[32][129];
    int vz = blockIdx.y;
    int xy0 = blockIdx.x * 32;
    int tid = threadIdx.x;
    #pragma unroll
    for (int i = 0; i < 16; i++) {
        int idx = tid + i * 256;
        int c = idx & 127, xyl = idx >> 7;
        int xy = xy0 + xyl;
        s[xyl][c] = (xy < NXY) ? scratch[((size_t)vz * NXY + xy) * CC + c] : 0.f;
    }
    __syncthreads();
    #pragma unroll
    for (int i = 0; i < 16; i++) {
        int idx = tid + i * 256;
        int xyl = idx & 31, c = idx >> 5;
        int xy = xy0 + xyl;
        if (xy < NXY) out[((size_t)vz * CC + c) * NXY + xy] = s[xyl][c];
    }
}

// ---------------- launcher ----------------
// Launch order puts gemm_conv (layer 1) at the 6th kernel launch: ncu -s 5 -c 1
// captures it, giving us the GEMM profile next round.
extern "C" void kernel_launch(void* const* d_in, const int* in_sizes, int n_in,
                              void* d_out, int out_size)
{
    const float* rot    = (const float*)d_in[0];
    const float* ctrans = (const float*)d_in[1];
    const float* intr   = (const float*)d_in[2];
    const float* prot   = (const float*)d_in[3];
    const float* ptrans = (const float*)d_in[4];
    const float* img    = (const float*)d_in[5];
    const float* w1 = (const float*)d_in[6];
    const float* b1 = (const float*)d_in[7];
    const float* g1 = (const float*)d_in[8];
    const float* be1= (const float*)d_in[9];
    const float* m1 = (const float*)d_in[10];
    const float* v1 = (const float*)d_in[11];
    const float* w2 = (const float*)d_in[12];
    const float* b2 = (const float*)d_in[13];
    const float* g2 = (const float*)d_in[14];
    const float* be2= (const float*)d_in[15];
    const float* m2 = (const float*)d_in[16];
    const float* v2 = (const float*)d_in[17];
    const float* w3 = (const float*)d_in[18];
    const float* b3 = (const float*)d_in[19];
    float* out = (float*)d_out;

    __half *actA, *actB, *wp1, *wp2, *wp3;
    float *logits, *ss, *scratch;
    cudaGetSymbolAddress((void**)&actA, g_actA);
    cudaGetSymbolAddress((void**)&actB, g_actB);
    cudaGetSymbolAddress((void**)&wp1, g_wp1);
    cudaGetSymbolAddress((void**)&wp2, g_wp2);
    cudaGetSymbolAddress((void**)&wp3, g_wp3);
    cudaGetSymbolAddress((void**)&logits, g_logits);
    cudaGetSymbolAddress((void**)&ss, g_ss);
    cudaGetSymbolAddress((void**)&scratch, g_scratch);

    cudaFuncSetAttribute(gemm_conv, cudaFuncAttributeMaxDynamicSharedMemorySize, SMEM_TOTAL);

    // kernels 1-5
    prep_w3x3<<<(9*KCH*256*64)/256, 256>>>(w1, wp1);
    prep_w3x3<<<(9*KCH*256*64)/256, 256>>>(w2, wp2);
    prep_w1x1<<<(KCH*256*64)/256, 256>>>(w3, wp3);
    dim3 cvgrid((HWPX + 63)/64, FCH/64, NCAM);
    convert_in<<<cvgrid, 256>>>(img, actA);
    prep_ss<<<1, 256>>>(b1,g1,be1,m1,v1, b2,g2,be2,m2,v2, b3);

    // kernel 6 = gemm layer 1 (ncu capture target)
    gemm_conv<<<NTILES, 512, SMEM_TOTAL>>>(actA, wp1, ss,        ss + 256, actB, nullptr, 9, 0);
    gemm_conv<<<NTILES, 512, SMEM_TOTAL>>>(actB, wp2, ss + 512,  ss + 768, actA, nullptr, 9, 0);
    gemm_conv<<<NTILES, 512, SMEM_TOTAL>>>(actA, wp3, ss + 1024, nullptr,  nullptr, logits, 1, 1);

    prep_mats<<<1, 32>>>(rot, ctrans, intr, prot, ptrans);
    cudaMemsetAsync(scratch, 0, sizeof(float)*(size_t)NZV*NXY*CC, 0);

    scatter_kernel<<<NPX, 128>>>(logits, scratch);

    bev_transpose<<<dim3((NXY + 31)/32, NZV), 256>>>(scratch, out);
}

// round 9
// speedup vs baseline: 4.7803x; 1.1495x over previous
#include <cuda_runtime.h>
#include <cuda_fp16.h>
#include <cstdint>
#include <math.h>

#define NCAM 4
#define FCH 256
#define IH 45
#define IW 80
#define HWPX (IH*IW)            // 3600
#define NPX (NCAM*HWPX)         // 14400
#define DD 99
#define CC 128
#define NXV 100
#define NYV 100
#define NZV 5
#define NXY (NXV*NYV)

#define TILES_PER_CAM 29        // ceil(3600/128)
#define NTILES (TILES_PER_CAM*NCAM)
#define KCH 8                   // 512/64 A-chunks per tap (fp16 2-term split)

// ---------------- scratch ----------------
__device__ __half g_actA[(size_t)NPX*512];   // [px][hi 256 | lo 256]
__device__ __half g_actB[(size_t)NPX*512];
__device__ __half g_wp1[9*4*256*64];         // weights stored once (shared by hi/lo)
__device__ __half g_wp2[9*4*256*64];
__device__ __half g_wp3[4*256*64];
__device__ float g_logits[(size_t)NPX*256];  // [px][227 used]
__device__ float g_ss[1280];
__device__ float g_mats[NCAM][24];
__device__ __align__(16) float g_scratch[(size_t)NZV*NXY*CC];  // [vz][xy][c]

// ---------------- helpers ----------------
__device__ __forceinline__ uint32_t smem_to_u32(const void* p) {
    uint32_t a;
    asm("{ .reg .u64 t; cvta.to.shared.u64 t, %1; cvt.u32.u64 %0, t; }" : "=r"(a) : "l"(p));
    return a;
}
__device__ __forceinline__ void cp_async16(uint32_t dst, const void* src, int sz) {
    asm volatile("cp.async.cg.shared.global [%0], [%1], 16, %2;"
                 :: "r"(dst), "l"(src), "r"(sz) : "memory");
}
__device__ __forceinline__ void cp_commit() { asm volatile("cp.async.commit_group;" ::: "memory"); }
__device__ __forceinline__ void cp_wait1()  { asm volatile("cp.async.wait_group 1;" ::: "memory"); }
__device__ __forceinline__ void cp_wait0()  { asm volatile("cp.async.wait_group 0;" ::: "memory"); }

__device__ __forceinline__ void ldmx4(uint32_t addr, uint32_t& r0, uint32_t& r1, uint32_t& r2, uint32_t& r3) {
    asm volatile("ldmatrix.sync.aligned.m8n8.x4.shared.b16 {%0,%1,%2,%3}, [%4];"
                 : "=r"(r0), "=r"(r1), "=r"(r2), "=r"(r3) : "r"(addr));
}
__device__ __forceinline__ void mma16816(float* d, const uint32_t* a, uint32_t b0, uint32_t b1) {
    asm volatile("mma.sync.aligned.m16n8k16.row.col.f32.f16.f16.f32 "
                 "{%0,%1,%2,%3}, {%4,%5,%6,%7}, {%8,%9}, {%0,%1,%2,%3};"
                 : "+f"(d[0]), "+f"(d[1]), "+f"(d[2]), "+f"(d[3])
                 : "r"(a[0]), "r"(a[1]), "r"(a[2]), "r"(a[3]), "r"(b0), "r"(b1));
}

// ---------------- smem layout for gemm kernel (3-stage) ----------------
#define RSTRIDE 144
#define OFF_SS   0
#define OFF_A0   2048
#define A_BYTES  (128*RSTRIDE)
#define B_BYTES  (256*RSTRIDE)
#define STAGE_BYTES (A_BYTES + B_BYTES)          // 55296
#define SMEM_TOTAL (OFF_A0 + 3*STAGE_BYTES)      // 167936

// ---------------- GEMM conv kernel (mma.sync fp16, fp32 accum) ----------------
__global__ __launch_bounds__(512, 1)
void gemm_conv(const __half* __restrict__ act_in,
               const __half* __restrict__ wp,
               const float* __restrict__ ssA, const float* __restrict__ ssB,
               __half* __restrict__ act_out,
               float* __restrict__ logits_out,
               int taps, int mode)
{
    extern __shared__ char smem[];
    uint32_t smem_base = smem_to_u32(smem);
    int tid = threadIdx.x;
    int wid = tid >> 5;
    int lane = tid & 31;

    int tile = blockIdx.x;
    int cam = tile / TILES_PER_CAM;
    int p0  = (tile % TILES_PER_CAM) * 128;

    {
        float* s_ss = (float*)smem;
        if (tid < 256) s_ss[tid] = ssA[tid];
        else           s_ss[tid] = ssB ? ssB[tid - 256] : 0.f;
    }

    const __half* abase = act_in + (size_t)cam * HWPX * 512;
    int nch = taps * KCH;

    int warp_m = wid >> 2, warp_n = wid & 3;
    int m0 = warp_m * 32;
    int n0 = warp_n * 64;

    float acc[2][8][4];
    #pragma unroll
    for (int a = 0; a < 2; a++)
        #pragma unroll
        for (int b = 0; b < 8; b++)
            #pragma unroll
            for (int c = 0; c < 4; c++) acc[a][b][c] = 0.f;

    int aseg = tid & 7;
    int ar0  = tid >> 3;
    int ar1  = ar0 + 64;
    int ap0  = p0 + ar0, ap1 = p0 + ar1;
    int ah0  = ap0 / IW, aw0 = ap0 % IW;
    int ah1  = ap1 / IW, aw1 = ap1 % IW;

    auto load_chunk = [&](int k, int stage) {
        uint32_t sa = smem_base + OFF_A0 + stage * STAGE_BYTES;
        uint32_t sb = sa + A_BYTES;
        int tap = k / KCH, kc = k % KCH;
        int dy = (taps == 9) ? (tap / 3 - 1) : 0;
        int dx = (taps == 9) ? (tap % 3 - 1) : 0;
        int secoff = (kc >> 2) * 256;          // xhi | xlo
        int cbase = (kc & 3) * 64;
        {
            int h2 = ah0 + dy, w2 = aw0 + dx;
            bool ok = (ap0 < HWPX) && (h2 >= 0) && (h2 < IH) && (w2 >= 0) && (w2 < IW);
            const __half* gp = ok
                ? (abase + (size_t)(h2 * IW + w2) * 512 + secoff + cbase + aseg * 8)
                : abase;
            cp_async16(sa + ar0 * RSTRIDE + aseg * 16, gp, ok ? 16 : 0);
        }
        {
            int h2 = ah1 + dy, w2 = aw1 + dx;
            bool ok = (ap1 < HWPX) && (h2 >= 0) && (h2 < IH) && (w2 >= 0) && (w2 < IW);
            const __half* gp = ok
                ? (abase + (size_t)(h2 * IW + w2) * 512 + secoff + cbase + aseg * 8)
                : abase;
            cp_async16(sa + ar1 * RSTRIDE + aseg * 16, gp, ok ? 16 : 0);
        }
        int kw = (taps == 9) ? (tap * 4 + (kc & 3)) : (kc & 3);
        const __half* wb = wp + (size_t)kw * (256 * 64);
        #pragma unroll
        for (int i = 0; i < 4; i++) {
            int idx = tid + i * 512;
            int r = idx >> 3, seg = idx & 7;
            cp_async16(sb + r * RSTRIDE + seg * 16, wb + r * 64 + seg * 8, 16);
        }
        cp_commit();
    };

    load_chunk(0, 0);
    if (nch > 1) load_chunk(1, 1);

    for (int k = 0; k < nch; k++) {
        if (k + 1 < nch) cp_wait1(); else cp_wait0();
        __syncthreads();
        if (k + 2 < nch) load_chunk(k + 2, (k + 2) % 3);

        uint32_t sa = smem_base + OFF_A0 + (k % 3) * STAGE_BYTES;
        uint32_t sb = sa + A_BYTES;
        uint32_t a_row = m0 + (lane & 15);
        uint32_t a_coloff = (lane >> 4) * 16;
        uint32_t b_row = n0 + (lane >> 4) * 8 + (lane & 7);
        uint32_t b_coloff = ((lane >> 3) & 1) * 16;

        #pragma unroll
        for (int kk = 0; kk < 4; kk++) {
            uint32_t af[2][4];
            #pragma unroll
            for (int mf = 0; mf < 2; mf++) {
                uint32_t addr = sa + (a_row + mf * 16) * RSTRIDE + kk * 32 + a_coloff;
                ldmx4(addr, af[mf][0], af[mf][1], af[mf][2], af[mf][3]);
            }
            uint32_t bf[4][4];
            #pragma unroll
            for (int nf2 = 0; nf2 < 4; nf2++) {
                uint32_t addr = sb + (b_row + nf2 * 16) * RSTRIDE + kk * 32 + b_coloff;
                ldmx4(addr, bf[nf2][0], bf[nf2][1], bf[nf2][2], bf[nf2][3]);
            }
            #pragma unroll
            for (int mf = 0; mf < 2; mf++)
                #pragma unroll
                for (int nf = 0; nf < 8; nf++)
                    mma16816(acc[mf][nf], af[mf], bf[nf >> 1][(nf & 1) * 2], bf[nf >> 1][(nf & 1) * 2 + 1]);
        }
    }

    const float* s_ss = (const float*)smem;
    int trow = lane >> 2;
    int tc   = (lane & 3) * 2;

    #pragma unroll
    for (int mf = 0; mf < 2; mf++) {
        #pragma unroll
        for (int hf = 0; hf < 2; hf++) {
            int pr = m0 + mf * 16 + hf * 8 + trow;
            int p = p0 + pr;
            if (p >= HWPX) continue;
            size_t pxg = (size_t)cam * HWPX + p;
            #pragma unroll
            for (int nf = 0; nf < 8; nf++) {
                int co = n0 + nf * 8 + tc;
                float d0 = acc[mf][nf][hf * 2];
                float d1 = acc[mf][nf][hf * 2 + 1];
                if (mode == 0) {
                    float y0 = fmaxf(d0 * s_ss[co]     + s_ss[256 + co],     0.f);
                    float y1 = fmaxf(d1 * s_ss[co + 1] + s_ss[256 + co + 1], 0.f);
                    __half h0 = __float2half_rn(y0);
                    __half h1 = __float2half_rn(y1);
                    __half l0 = __float2half_rn(y0 - __half2float(h0));
                    __half l1 = __float2half_rn(y1 - __half2float(h1));
                    __half* outp = act_out + pxg * 512 + co;
                    *(__half2*)(outp)       = __halves2half2(h0, h1);
                    *(__half2*)(outp + 256) = __halves2half2(l0, l1);
                } else {
                    float2 v = make_float2(d0 + s_ss[co], d1 + s_ss[co + 1]);
                    *(float2*)(logits_out + pxg * 256 + co) = v;
                }
            }
        }
    }
}

// ---------------- input conversion: NCHW fp32 -> NHWC fp16 hi/lo ----------------
__global__ __launch_bounds__(256)
void convert_in(const float* __restrict__ img, __half* __restrict__ out)
{
    __shared__ float s[64][65];
    int n = blockIdx.z;
    int ci0 = blockIdx.y * 64;
    int p0 = blockIdx.x * 64;
    int tid = threadIdx.x;
    for (int idx = tid; idx < 64 * 64; idx += 256) {
        int ci = idx / 64, p = idx % 64;
        float v = 0.f;
        if (p0 + p < HWPX) v = img[((size_t)(n * FCH + ci0 + ci)) * HWPX + p0 + p];
        s[ci][p] = v;
    }
    __syncthreads();
    for (int idx = tid; idx < 64 * 64; idx += 256) {
        int p = idx / 64, ci = idx % 64;
        if (p0 + p >= HWPX) continue;
        float v = s[ci][p];
        __half hi = __float2half_rn(v);
        __half lo = __float2half_rn(v - __half2float(hi));
        size_t base = ((size_t)n * HWPX + p0 + p) * 512 + ci0 + ci;
        out[base] = hi;
        out[base + 256] = lo;
    }
}

// ---------------- weight prep (stored once; kc in 0..3) ----------------
__global__ void prep_w3x3(const float* __restrict__ w, __half* __restrict__ wp)
{
    int idx = blockIdx.x * 256 + threadIdx.x;
    if (idx >= 9 * 4 * 256 * 64) return;
    int j   = idx & 63;
    int co  = (idx >> 6) & 255;
    int kc  = (idx >> 14) & 3;
    int tap = idx >> 16;
    int ci = kc * 64 + j;
    int ky = tap / 3, kx = tap % 3;
    float v = w[(((size_t)co * 256 + ci) * 3 + ky) * 3 + kx];
    wp[idx] = __float2half_rn(v);
}

__global__ void prep_w1x1(const float* __restrict__ w, __half* __restrict__ wp)
{
    int idx = blockIdx.x * 256 + threadIdx.x;
    if (idx >= 4 * 256 * 64) return;
    int j  = idx & 63;
    int co = (idx >> 6) & 255;
    int kc = idx >> 14;
    int ci = kc * 64 + j;
    float v = (co < 227) ? w[(size_t)co * 256 + ci] : 0.f;
    wp[idx] = __float2half_rn(v);
}

__global__ void prep_ss(const float* b1, const float* g1, const float* be1, const float* m1, const float* v1,
                        const float* b2, const float* g2, const float* be2, const float* m2, const float* v2,
                        const float* b3)
{
    int c = threadIdx.x;
    float s1 = g1[c] * rsqrtf(v1[c] + 1e-3f);
    g_ss[c] = s1;
    g_ss[256 + c] = be1[c] + (b1[c] - m1[c]) * s1;
    float s2 = g2[c] * rsqrtf(v2[c] + 1e-3f);
    g_ss[512 + c] = s2;
    g_ss[768 + c] = be2[c] + (b2[c] - m2[c]) * s2;
    g_ss[1024 + c] = (c < 227) ? b3[c] : 0.f;
}

// ---------------- per-camera matrices ----------------
__device__ void inv3(const float* a, float* o) {
    float det = a[0]*(a[4]*a[8]-a[5]*a[7]) - a[1]*(a[3]*a[8]-a[5]*a[6]) + a[2]*(a[3]*a[7]-a[4]*a[6]);
    float id = 1.0f/det;
    o[0]=(a[4]*a[8]-a[5]*a[7])*id; o[1]=(a[2]*a[7]-a[1]*a[8])*id; o[2]=(a[1]*a[5]-a[2]*a[4])*id;
    o[3]=(a[5]*a[6]-a[3]*a[8])*id; o[4]=(a[0]*a[8]-a[2]*a[6])*id; o[5]=(a[2]*a[3]-a[0]*a[5])*id;
    o[6]=(a[3]*a[7]-a[4]*a[6])*id; o[7]=(a[1]*a[6]-a[0]*a[7])*id; o[8]=(a[0]*a[4]-a[1]*a[3])*id;
}

__global__ void prep_mats(const float* __restrict__ rot, const float* __restrict__ ctrans,
                          const float* __restrict__ intr, const float* __restrict__ prot,
                          const float* __restrict__ ptrans) {
    int n = threadIdx.x;
    if (n >= NCAM) return;
    float invK[9], invPR[9];
    inv3(intr + n*9, invK);
    inv3(prot + n*9, invPR);
    const float* R = rot + n*9;
    float* m = g_mats[n];
    #pragma unroll
    for (int i=0;i<3;i++)
        #pragma unroll
        for (int j=0;j<3;j++){
            float s=0.f;
            #pragma unroll
            for (int k2=0;k2<3;k2++) s += R[i*3+k2]*invK[k2*3+j];
            m[i*3+j]=s;
        }
    #pragma unroll
    for (int i=0;i<9;i++) m[9+i]=invPR[i];
    #pragma unroll
    for (int i=0;i<3;i++){ m[18+i]=ptrans[n*3+i]; m[21+i]=ctrans[n*3+i]; }
}

// ---------------- fused softmax + geometry + quad-merged scatter ----------------
// Block = 4 rays (consecutive w, same h). Runs from all 4 rays are deduped by
// voxel id; each distinct voxel is flushed ONCE with red.v4 combining rays.
#define MAXE (4*DD)   // 396
__global__ __launch_bounds__(128)
void scatter_kernel(const float* __restrict__ logits, float* __restrict__ scratch)
{
    __shared__ float s_m[24];
    __shared__ float s_p[4][DD];
    __shared__ int   s_vox[4][DD];
    __shared__ __align__(16) float s_ctx[4][CC];
    __shared__ int   s_evox[MAXE];
    __shared__ int   s_eray[MAXE];
    __shared__ float s_ew[MAXE];
    __shared__ float s_lw[MAXE*4];
    __shared__ int   s_lead[MAXE];
    __shared__ int   s_n;

    int blk = blockIdx.x;
    int n   = blk / (HWPX/4);
    int q   = blk % (HWPX/4);
    int h   = q / (IW/4);
    int w0  = (q % (IW/4)) * 4;
    int t = threadIdx.x, lane = t & 31, warp = t >> 5;

    if (t < 24) s_m[t] = g_mats[n][t];
    if (t == 0) s_n = 0;
    const float* lgbase = logits + ((size_t)n * HWPX + h * IW + w0) * 256;
    #pragma unroll
    for (int r = 0; r < 4; r++)
        s_ctx[r][t] = lgbase[r * 256 + DD + t];
    __syncthreads();

    // ---- phase 1: warp r handles ray (h, w0+r) ----
    {
        int r = warp;
        const float* lg = lgbase + r * 256;
        float xv[4];
        float lmax = -1e30f;
        #pragma unroll
        for (int j = 0; j < 4; j++) {
            int d = lane + 32 * j;
            xv[j] = (d < DD) ? lg[d] : -1e30f;
            lmax = fmaxf(lmax, xv[j]);
        }
        #pragma unroll
        for (int o = 16; o; o >>= 1) lmax = fmaxf(lmax, __shfl_xor_sync(0xffffffffu, lmax, o));
        float ev[4], lsum = 0.f;
        #pragma unroll
        for (int j = 0; j < 4; j++) {
            int d = lane + 32 * j;
            ev[j] = (d < DD) ? __expf(xv[j] - lmax) : 0.f;
            lsum += ev[j];
        }
        #pragma unroll
        for (int o = 16; o; o >>= 1) lsum += __shfl_xor_sync(0xffffffffu, lsum, o);
        float inv = 1.f / lsum;

        float fx = (w0 + r) * (639.0f / 79.0f);
        float fy = h * (359.0f / 44.0f);
        #pragma unroll
        for (int j = 0; j < 4; j++) {
            int d = lane + 32 * j;
            if (d >= DD) continue;
            s_p[r][d] = ev[j] * inv;
            float dv = (float)(d + 1);
            float q0 = fx - s_m[18], q1 = fy - s_m[19], q2 = dv - s_m[20];
            float r0 = s_m[ 9]*q0 + s_m[10]*q1 + s_m[11]*q2;
            float r1 = s_m[12]*q0 + s_m[13]*q1 + s_m[14]*q2;
            float r2 = s_m[15]*q0 + s_m[16]*q1 + s_m[17]*q2;
            float t0 = r0*r2, t1 = r1*r2, t2 = r2;
            float gx = s_m[0]*t0 + s_m[1]*t1 + s_m[2]*t2 + s_m[21];
            float gy = s_m[3]*t0 + s_m[4]*t1 + s_m[5]*t2 + s_m[22];
            float gz = s_m[6]*t0 + s_m[7]*t1 + s_m[8]*t2 + s_m[23];
            int vx = (int)floorf(gx * 0.5f);
            int vy = (int)floorf((gy + 100.f) * 0.5f);
            int vz = (int)floorf((gz + 10.f) * 0.25f);
            bool kept = (vx>=0 && vx<NXV && vy>=0 && vy<NYV && vz>=0 && vz<NZV);
            s_vox[r][d] = kept ? (vz*NXY + vx*NYV + vy) : -1;
        }
        __syncwarp();
        // run leaders append (vox, ray, wsum)
        #pragma unroll
        for (int j = 0; j < 4; j++) {
            int d = lane + 32 * j;
            if (d >= DD) continue;
            int v = s_vox[r][d];
            if (v < 0) continue;
            bool f = (d == 0) || (s_vox[r][d-1] != v);
            if (!f) continue;
            float wsum = s_p[r][d];
            int dd = d + 1;
            while (dd < DD && s_vox[r][dd] == v) { wsum += s_p[r][dd]; dd++; }
            int idx = atomicAdd(&s_n, 1);
            s_evox[idx] = v;
            s_eray[idx] = r;
            s_ew[idx]   = wsum;
        }
    }
    __syncthreads();

    int N = s_n;
    for (int i = t; i < N * 4; i += 128) s_lw[i] = 0.f;
    __syncthreads();

    // ---- phase 2: first-occurrence dedup ----
    for (int i = t; i < N; i += 128) {
        int v = s_evox[i];
        int first = i;
        for (int j = 0; j < i; j++)
            if (s_evox[j] == v) { first = j; break; }
        s_lead[i] = (first == i) ? 1 : 0;
        atomicAdd(&s_lw[first * 4 + s_eray[i]], s_ew[i]);
    }
    __syncthreads();

    // ---- phase 3: flush distinct voxels ----
    float4 c0 = ((const float4*)s_ctx[0])[lane];
    float4 c1 = ((const float4*)s_ctx[1])[lane];
    float4 c2 = ((const float4*)s_ctx[2])[lane];
    float4 c3 = ((const float4*)s_ctx[3])[lane];
    for (int e = warp; e < N; e += 4) {
        if (!s_lead[e]) continue;
        float a0 = s_lw[e*4], a1 = s_lw[e*4+1], a2 = s_lw[e*4+2], a3 = s_lw[e*4+3];
        float vx = a0*c0.x + a1*c1.x + a2*c2.x + a3*c3.x;
        float vy = a0*c0.y + a1*c1.y + a2*c2.y + a3*c3.y;
        float vz = a0*c0.z + a1*c1.z + a2*c2.z + a3*c3.z;
        float vw = a0*c0.w + a1*c1.w + a2*c2.w + a3*c3.w;
        float* ptr = scratch + (size_t)s_evox[e] * CC + lane * 4;
        asm volatile("red.global.add.v4.f32 [%0], {%1,%2,%3,%4};"
                     :: "l"(ptr), "f"(vx), "f"(vy), "f"(vz), "f"(vw)
                     : "memory");
    }
}

// ---------------- scratch [vz][xy][c] -> out [vz][c][xy] ----------------
__global__ __launch_bounds__(256)
void bev_transpose(const float* __restrict__ scratch, float* __restrict__ out)
{
    __shared__ float s[32][129];
    int vz = blockIdx.y;
    int xy0 = blockIdx.x * 32;
    int tid = threadIdx.x;
    #pragma unroll
    for (int i = 0; i < 16; i++) {
        int idx = tid + i * 256;
        int c = idx & 127, xyl = idx >> 7;
        int xy = xy0 + xyl;
        s[xyl][c] = (xy < NXY) ? scratch[((size_t)vz * NXY + xy) * CC + c] : 0.f;
    }
    __syncthreads();
    #pragma unroll
    for (int i = 0; i < 16; i++) {
        int idx = tid + i * 256;
        int xyl = idx & 31, c = idx >> 5;
        int xy = xy0 + xyl;
        if (xy < NXY) out[((size_t)vz * CC + c) * NXY + xy] = s[xyl][c];
    }
}

// ---------------- launcher ----------------
extern "C" void kernel_launch(void* const* d_in, const int* in_sizes, int n_in,
                              void* d_out, int out_size)
{
    const float* rot    = (const float*)d_in[0];
    const float* ctrans = (const float*)d_in[1];
    const float* intr   = (const float*)d_in[2];
    const float* prot   = (const float*)d_in[3];
    const float* ptrans = (const float*)d_in[4];
    const float* img    = (const float*)d_in[5];
    const float* w1 = (const float*)d_in[6];
    const float* b1 = (const float*)d_in[7];
    const float* g1 = (const float*)d_in[8];
    const float* be1= (const float*)d_in[9];
    const float* m1 = (const float*)d_in[10];
    const float* v1 = (const float*)d_in[11];
    const float* w2 = (const float*)d_in[12];
    const float* b2 = (const float*)d_in[13];
    const float* g2 = (const float*)d_in[14];
    const float* be2= (const float*)d_in[15];
    const float* m2 = (const float*)d_in[16];
    const float* v2 = (const float*)d_in[17];
    const float* w3 = (const float*)d_in[18];
    const float* b3 = (const float*)d_in[19];
    float* out = (float*)d_out;

    __half *actA, *actB, *wp1, *wp2, *wp3;
    float *logits, *ss, *scratch;
    cudaGetSymbolAddress((void**)&actA, g_actA);
    cudaGetSymbolAddress((void**)&actB, g_actB);
    cudaGetSymbolAddress((void**)&wp1, g_wp1);
    cudaGetSymbolAddress((void**)&wp2, g_wp2);
    cudaGetSymbolAddress((void**)&wp3, g_wp3);
    cudaGetSymbolAddress((void**)&logits, g_logits);
    cudaGetSymbolAddress((void**)&ss, g_ss);
    cudaGetSymbolAddress((void**)&scratch, g_scratch);

    cudaFuncSetAttribute(gemm_conv, cudaFuncAttributeMaxDynamicSharedMemorySize, SMEM_TOTAL);

    prep_w3x3<<<(9*4*256*64)/256, 256>>>(w1, wp1);
    prep_w3x3<<<(9*4*256*64)/256, 256>>>(w2, wp2);
    prep_w1x1<<<(4*256*64)/256, 256>>>(w3, wp3);
    dim3 cvgrid((HWPX + 63)/64, FCH/64, NCAM);
    convert_in<<<cvgrid, 256>>>(img, actA);
    prep_ss<<<1, 256>>>(b1,g1,be1,m1,v1, b2,g2,be2,m2,v2, b3);

    gemm_conv<<<NTILES, 512, SMEM_TOTAL>>>(actA, wp1, ss,        ss + 256, actB, nullptr, 9, 0);
    gemm_conv<<<NTILES, 512, SMEM_TOTAL>>>(actB, wp2, ss + 512,  ss + 768, actA, nullptr, 9, 0);
    gemm_conv<<<NTILES, 512, SMEM_TOTAL>>>(actA, wp3, ss + 1024, nullptr,  nullptr, logits, 1, 1);

    prep_mats<<<1, 32>>>(rot, ctrans, intr, prot, ptrans);
    cudaMemsetAsync(scratch, 0, sizeof(float)*(size_t)NZV*NXY*CC, 0);

    scatter_kernel<<<NPX/4, 128>>>(logits, scratch);

    bev_transpose<<<dim3((NXY + 31)/32, NZV), 256>>>(scratch, out);
}

// round 10
// speedup vs baseline: 7.3984x; 1.5477x over previous
#include <cuda_runtime.h>
#include <cuda_fp16.h>
#include <cstdint>
#include <math.h>

#define NCAM 4
#define FCH 256
#define IH 45
#define IW 80
#define HWPX (IH*IW)            // 3600
#define NPX (NCAM*HWPX)         // 14400
#define DD 99
#define CC 128
#define NXV 100
#define NYV 100
#define NZV 5
#define NXY (NXV*NYV)

#define TILES_PER_CAM 29        // ceil(3600/128)
#define NTILES (TILES_PER_CAM*NCAM)
#define KCH 4                   // 256/64 A-chunks per tap (pure fp16)

// ---------------- scratch ----------------
__device__ __half g_actA[(size_t)NPX*256];   // [px][256] fp16
__device__ __half g_actB[(size_t)NPX*256];
__device__ __half g_wp1[9*4*256*64];
__device__ __half g_wp2[9*4*256*64];
__device__ __half g_wp3[4*256*64];
__device__ float g_logits[(size_t)NPX*256];  // [px][227 used]
__device__ float g_ss[1280];
__device__ float g_mats[NCAM][24];
__device__ __align__(16) float g_scratch[(size_t)NZV*NXY*CC];  // [vz][xy][c]

// ---------------- helpers ----------------
__device__ __forceinline__ uint32_t smem_to_u32(const void* p) {
    uint32_t a;
    asm("{ .reg .u64 t; cvta.to.shared.u64 t, %1; cvt.u32.u64 %0, t; }" : "=r"(a) : "l"(p));
    return a;
}
__device__ __forceinline__ void cp_async16(uint32_t dst, const void* src, int sz) {
    asm volatile("cp.async.cg.shared.global [%0], [%1], 16, %2;"
                 :: "r"(dst), "l"(src), "r"(sz) : "memory");
}
__device__ __forceinline__ void cp_commit() { asm volatile("cp.async.commit_group;" ::: "memory"); }
__device__ __forceinline__ void cp_wait1()  { asm volatile("cp.async.wait_group 1;" ::: "memory"); }
__device__ __forceinline__ void cp_wait0()  { asm volatile("cp.async.wait_group 0;" ::: "memory"); }

__device__ __forceinline__ void ldmx4(uint32_t addr, uint32_t& r0, uint32_t& r1, uint32_t& r2, uint32_t& r3) {
    asm volatile("ldmatrix.sync.aligned.m8n8.x4.shared.b16 {%0,%1,%2,%3}, [%4];"
                 : "=r"(r0), "=r"(r1), "=r"(r2), "=r"(r3) : "r"(addr));
}
__device__ __forceinline__ void mma16816(float* d, const uint32_t* a, uint32_t b0, uint32_t b1) {
    asm volatile("mma.sync.aligned.m16n8k16.row.col.f32.f16.f16.f32 "
                 "{%0,%1,%2,%3}, {%4,%5,%6,%7}, {%8,%9}, {%0,%1,%2,%3};"
                 : "+f"(d[0]), "+f"(d[1]), "+f"(d[2]), "+f"(d[3])
                 : "r"(a[0]), "r"(a[1]), "r"(a[2]), "r"(a[3]), "r"(b0), "r"(b1));
}

// ---------------- smem layout for gemm kernel (3-stage) ----------------
#define RSTRIDE 144
#define OFF_SS   0
#define OFF_A0   2048
#define A_BYTES  (128*RSTRIDE)
#define B_BYTES  (256*RSTRIDE)
#define STAGE_BYTES (A_BYTES + B_BYTES)          // 55296
#define SMEM_TOTAL (OFF_A0 + 3*STAGE_BYTES)      // 167936

// ---------------- GEMM conv kernel (mma.sync fp16, fp32 accum) ----------------
__global__ __launch_bounds__(512, 1)
void gemm_conv(const __half* __restrict__ act_in,
               const __half* __restrict__ wp,
               const float* __restrict__ ssA, const float* __restrict__ ssB,
               __half* __restrict__ act_out,
               float* __restrict__ logits_out,
               int taps, int mode)
{
    extern __shared__ char smem[];
    uint32_t smem_base = smem_to_u32(smem);
    int tid = threadIdx.x;
    int wid = tid >> 5;
    int lane = tid & 31;

    int tile = blockIdx.x;
    int cam = tile / TILES_PER_CAM;
    int p0  = (tile % TILES_PER_CAM) * 128;

    {
        float* s_ss = (float*)smem;
        if (tid < 256) s_ss[tid] = ssA[tid];
        else           s_ss[tid] = ssB ? ssB[tid - 256] : 0.f;
    }

    const __half* abase = act_in + (size_t)cam * HWPX * 256;
    int nch = taps * KCH;

    int warp_m = wid >> 2, warp_n = wid & 3;
    int m0 = warp_m * 32;
    int n0 = warp_n * 64;

    float acc[2][8][4];
    #pragma unroll
    for (int a = 0; a < 2; a++)
        #pragma unroll
        for (int b = 0; b < 8; b++)
            #pragma unroll
            for (int c = 0; c < 4; c++) acc[a][b][c] = 0.f;

    int aseg = tid & 7;
    int ar0  = tid >> 3;
    int ar1  = ar0 + 64;
    int ap0  = p0 + ar0, ap1 = p0 + ar1;
    int ah0  = ap0 / IW, aw0 = ap0 % IW;
    int ah1  = ap1 / IW, aw1 = ap1 % IW;

    auto load_chunk = [&](int k, int stage) {
        uint32_t sa = smem_base + OFF_A0 + stage * STAGE_BYTES;
        uint32_t sb = sa + A_BYTES;
        int tap = k / KCH, kc = k % KCH;
        int dy = (taps == 9) ? (tap / 3 - 1) : 0;
        int dx = (taps == 9) ? (tap % 3 - 1) : 0;
        int cbase = kc * 64;
        {
            int h2 = ah0 + dy, w2 = aw0 + dx;
            bool ok = (ap0 < HWPX) && (h2 >= 0) && (h2 < IH) && (w2 >= 0) && (w2 < IW);
            const __half* gp = ok
                ? (abase + (size_t)(h2 * IW + w2) * 256 + cbase + aseg * 8)
                : abase;
            cp_async16(sa + ar0 * RSTRIDE + aseg * 16, gp, ok ? 16 : 0);
        }
        {
            int h2 = ah1 + dy, w2 = aw1 + dx;
            bool ok = (ap1 < HWPX) && (h2 >= 0) && (h2 < IH) && (w2 >= 0) && (w2 < IW);
            const __half* gp = ok
                ? (abase + (size_t)(h2 * IW + w2) * 256 + cbase + aseg * 8)
                : abase;
            cp_async16(sa + ar1 * RSTRIDE + aseg * 16, gp, ok ? 16 : 0);
        }
        const __half* wb = wp + (size_t)k * (256 * 64);
        #pragma unroll
        for (int i = 0; i < 4; i++) {
            int idx = tid + i * 512;
            int r = idx >> 3, seg = idx & 7;
            cp_async16(sb + r * RSTRIDE + seg * 16, wb + r * 64 + seg * 8, 16);
        }
        cp_commit();
    };

    load_chunk(0, 0);
    if (nch > 1) load_chunk(1, 1);

    for (int k = 0; k < nch; k++) {
        if (k + 1 < nch) cp_wait1(); else cp_wait0();
        __syncthreads();
        if (k + 2 < nch) load_chunk(k + 2, (k + 2) % 3);

        uint32_t sa = smem_base + OFF_A0 + (k % 3) * STAGE_BYTES;
        uint32_t sb = sa + A_BYTES;
        uint32_t a_row = m0 + (lane & 15);
        uint32_t a_coloff = (lane >> 4) * 16;
        uint32_t b_row = n0 + (lane >> 4) * 8 + (lane & 7);
        uint32_t b_coloff = ((lane >> 3) & 1) * 16;

        #pragma unroll
        for (int kk = 0; kk < 4; kk++) {
            uint32_t af[2][4];
            #pragma unroll
            for (int mf = 0; mf < 2; mf++) {
                uint32_t addr = sa + (a_row + mf * 16) * RSTRIDE + kk * 32 + a_coloff;
                ldmx4(addr, af[mf][0], af[mf][1], af[mf][2], af[mf][3]);
            }
            uint32_t bf[4][4];
            #pragma unroll
            for (int nf2 = 0; nf2 < 4; nf2++) {
                uint32_t addr = sb + (b_row + nf2 * 16) * RSTRIDE + kk * 32 + b_coloff;
                ldmx4(addr, bf[nf2][0], bf[nf2][1], bf[nf2][2], bf[nf2][3]);
            }
            #pragma unroll
            for (int mf = 0; mf < 2; mf++)
                #pragma unroll
                for (int nf = 0; nf < 8; nf++)
                    mma16816(acc[mf][nf], af[mf], bf[nf >> 1][(nf & 1) * 2], bf[nf >> 1][(nf & 1) * 2 + 1]);
        }
    }

    const float* s_ss = (const float*)smem;
    int trow = lane >> 2;
    int tc   = (lane & 3) * 2;

    #pragma unroll
    for (int mf = 0; mf < 2; mf++) {
        #pragma unroll
        for (int hf = 0; hf < 2; hf++) {
            int pr = m0 + mf * 16 + hf * 8 + trow;
            int p = p0 + pr;
            if (p >= HWPX) continue;
            size_t pxg = (size_t)cam * HWPX + p;
            #pragma unroll
            for (int nf = 0; nf < 8; nf++) {
                int co = n0 + nf * 8 + tc;
                float d0 = acc[mf][nf][hf * 2];
                float d1 = acc[mf][nf][hf * 2 + 1];
                if (mode == 0) {
                    float y0 = fmaxf(d0 * s_ss[co]     + s_ss[256 + co],     0.f);
                    float y1 = fmaxf(d1 * s_ss[co + 1] + s_ss[256 + co + 1], 0.f);
                    *(__half2*)(act_out + pxg * 256 + co) =
                        __halves2half2(__float2half_rn(y0), __float2half_rn(y1));
                } else {
                    float2 v = make_float2(d0 + s_ss[co], d1 + s_ss[co + 1]);
                    *(float2*)(logits_out + pxg * 256 + co) = v;
                }
            }
        }
    }
}

// ---------------- input conversion: NCHW fp32 -> NHWC fp16 ----------------
__global__ __launch_bounds__(256)
void convert_in(const float* __restrict__ img, __half* __restrict__ out)
{
    __shared__ float s[64][65];
    int n = blockIdx.z;
    int ci0 = blockIdx.y * 64;
    int p0 = blockIdx.x * 64;
    int tid = threadIdx.x;
    for (int idx = tid; idx < 64 * 64; idx += 256) {
        int ci = idx / 64, p = idx % 64;
        float v = 0.f;
        if (p0 + p < HWPX) v = img[((size_t)(n * FCH + ci0 + ci)) * HWPX + p0 + p];
        s[ci][p] = v;
    }
    __syncthreads();
    for (int idx = tid; idx < 64 * 64; idx += 256) {
        int p = idx / 64, ci = idx % 64;
        if (p0 + p >= HWPX) continue;
        out[((size_t)n * HWPX + p0 + p) * 256 + ci0 + ci] = __float2half_rn(s[ci][p]);
    }
}

// ---------------- weight prep ----------------
__global__ void prep_w3x3(const float* __restrict__ w, __half* __restrict__ wp)
{
    int idx = blockIdx.x * 256 + threadIdx.x;
    if (idx >= 9 * 4 * 256 * 64) return;
    int j   = idx & 63;
    int co  = (idx >> 6) & 255;
    int kc  = (idx >> 14) & 3;
    int tap = idx >> 16;
    int ci = kc * 64 + j;
    int ky = tap / 3, kx = tap % 3;
    float v = w[(((size_t)co * 256 + ci) * 3 + ky) * 3 + kx];
    wp[idx] = __float2half_rn(v);
}

__global__ void prep_w1x1(const float* __restrict__ w, __half* __restrict__ wp)
{
    int idx = blockIdx.x * 256 + threadIdx.x;
    if (idx >= 4 * 256 * 64) return;
    int j  = idx & 63;
    int co = (idx >> 6) & 255;
    int kc = idx >> 14;
    int ci = kc * 64 + j;
    float v = (co < 227) ? w[(size_t)co * 256 + ci] : 0.f;
    wp[idx] = __float2half_rn(v);
}

__global__ void prep_ss(const float* b1, const float* g1, const float* be1, const float* m1, const float* v1,
                        const float* b2, const float* g2, const float* be2, const float* m2, const float* v2,
                        const float* b3)
{
    int c = threadIdx.x;
    float s1 = g1[c] * rsqrtf(v1[c] + 1e-3f);
    g_ss[c] = s1;
    g_ss[256 + c] = be1[c] + (b1[c] - m1[c]) * s1;
    float s2 = g2[c] * rsqrtf(v2[c] + 1e-3f);
    g_ss[512 + c] = s2;
    g_ss[768 + c] = be2[c] + (b2[c] - m2[c]) * s2;
    g_ss[1024 + c] = (c < 227) ? b3[c] : 0.f;
}

// ---------------- per-camera matrices ----------------
__device__ void inv3(const float* a, float* o) {
    float det = a[0]*(a[4]*a[8]-a[5]*a[7]) - a[1]*(a[3]*a[8]-a[5]*a[6]) + a[2]*(a[3]*a[7]-a[4]*a[6]);
    float id = 1.0f/det;
    o[0]=(a[4]*a[8]-a[5]*a[7])*id; o[1]=(a[2]*a[7]-a[1]*a[8])*id; o[2]=(a[1]*a[5]-a[2]*a[4])*id;
    o[3]=(a[5]*a[6]-a[3]*a[8])*id; o[4]=(a[0]*a[8]-a[2]*a[6])*id; o[5]=(a[2]*a[3]-a[0]*a[5])*id;
    o[6]=(a[3]*a[7]-a[4]*a[6])*id; o[7]=(a[1]*a[6]-a[0]*a[7])*id; o[8]=(a[0]*a[4]-a[1]*a[3])*id;
}

__global__ void prep_mats(const float* __restrict__ rot, const float* __restrict__ ctrans,
                          const float* __restrict__ intr, const float* __restrict__ prot,
                          const float* __restrict__ ptrans) {
    int n = threadIdx.x;
    if (n >= NCAM) return;
    float invK[9], invPR[9];
    inv3(intr + n*9, invK);
    inv3(prot + n*9, invPR);
    const float* R = rot + n*9;
    float* m = g_mats[n];
    #pragma unroll
    for (int i=0;i<3;i++)
        #pragma unroll
        for (int j=0;j<3;j++){
            float s=0.f;
            #pragma unroll
            for (int k2=0;k2<3;k2++) s += R[i*3+k2]*invK[k2*3+j];
            m[i*3+j]=s;
        }
    #pragma unroll
    for (int i=0;i<9;i++) m[9+i]=invPR[i];
    #pragma unroll
    for (int i=0;i<3;i++){ m[18+i]=ptrans[n*3+i]; m[21+i]=ctrans[n*3+i]; }
}

// ---------------- fused softmax + geometry + quad-merged scatter ----------------
#define MAXE (4*DD)   // 396
__global__ __launch_bounds__(128)
void scatter_kernel(const float* __restrict__ logits, float* __restrict__ scratch)
{
    __shared__ float s_m[24];
    __shared__ float s_p[4][DD];
    __shared__ int   s_vox[4][DD];
    __shared__ __align__(16) float s_ctx[4][CC];
    __shared__ int   s_evox[MAXE];
    __shared__ int   s_eray[MAXE];
    __shared__ float s_ew[MAXE];
    __shared__ float s_lw[MAXE*4];
    __shared__ int   s_lead[MAXE];
    __shared__ int   s_n;

    int blk = blockIdx.x;
    int n   = blk / (HWPX/4);
    int q   = blk % (HWPX/4);
    int h   = q / (IW/4);
    int w0  = (q % (IW/4)) * 4;
    int t = threadIdx.x, lane = t & 31, warp = t >> 5;

    if (t < 24) s_m[t] = g_mats[n][t];
    if (t == 0) s_n = 0;
    const float* lgbase = logits + ((size_t)n * HWPX + h * IW + w0) * 256;
    #pragma unroll
    for (int r = 0; r < 4; r++)
        s_ctx[r][t] = lgbase[r * 256 + DD + t];
    __syncthreads();

    {
        int r = warp;
        const float* lg = lgbase + r * 256;
        float xv[4];
        float lmax = -1e30f;
        #pragma unroll
        for (int j = 0; j < 4; j++) {
            int d = lane + 32 * j;
            xv[j] = (d < DD) ? lg[d] : -1e30f;
            lmax = fmaxf(lmax, xv[j]);
        }
        #pragma unroll
        for (int o = 16; o; o >>= 1) lmax = fmaxf(lmax, __shfl_xor_sync(0xffffffffu, lmax, o));
        float ev[4], lsum = 0.f;
        #pragma unroll
        for (int j = 0; j < 4; j++) {
            int d = lane + 32 * j;
            ev[j] = (d < DD) ? __expf(xv[j] - lmax) : 0.f;
            lsum += ev[j];
        }
        #pragma unroll
        for (int o = 16; o; o >>= 1) lsum += __shfl_xor_sync(0xffffffffu, lsum, o);
        float inv = 1.f / lsum;

        float fx = (w0 + r) * (639.0f / 79.0f);
        float fy = h * (359.0f / 44.0f);
        #pragma unroll
        for (int j = 0; j < 4; j++) {
            int d = lane + 32 * j;
            if (d >= DD) continue;
            s_p[r][d] = ev[j] * inv;
            float dv = (float)(d + 1);
            float q0 = fx - s_m[18], q1 = fy - s_m[19], q2 = dv - s_m[20];
            float r0 = s_m[ 9]*q0 + s_m[10]*q1 + s_m[11]*q2;
            float r1 = s_m[12]*q0 + s_m[13]*q1 + s_m[14]*q2;
            float r2 = s_m[15]*q0 + s_m[16]*q1 + s_m[17]*q2;
            float t0 = r0*r2, t1 = r1*r2, t2 = r2;
            float gx = s_m[0]*t0 + s_m[1]*t1 + s_m[2]*t2 + s_m[21];
            float gy = s_m[3]*t0 + s_m[4]*t1 + s_m[5]*t2 + s_m[22];
            float gz = s_m[6]*t0 + s_m[7]*t1 + s_m[8]*t2 + s_m[23];
            int vx = (int)floorf(gx * 0.5f);
            int vy = (int)floorf((gy + 100.f) * 0.5f);
            int vz = (int)floorf((gz + 10.f) * 0.25f);
            bool kept = (vx>=0 && vx<NXV && vy>=0 && vy<NYV && vz>=0 && vz<NZV);
            s_vox[r][d] = kept ? (vz*NXY + vx*NYV + vy) : -1;
        }
        __syncwarp();
        #pragma unroll
        for (int j = 0; j < 4; j++) {
            int d = lane + 32 * j;
            if (d >= DD) continue;
            int v = s_vox[r][d];
            if (v < 0) continue;
            bool f = (d == 0) || (s_vox[r][d-1] != v);
            if (!f) continue;
            float wsum = s_p[r][d];
            int dd = d + 1;
            while (dd < DD && s_vox[r][dd] == v) { wsum += s_p[r][dd]; dd++; }
            int idx = atomicAdd(&s_n, 1);
            s_evox[idx] = v;
            s_eray[idx] = r;
            s_ew[idx]   = wsum;
        }
    }
    __syncthreads();

    int N = s_n;
    for (int i = t; i < N * 4; i += 128) s_lw[i] = 0.f;
    __syncthreads();

    for (int i = t; i < N; i += 128) {
        int v = s_evox[i];
        int first = i;
        for (int j = 0; j < i; j++)
            if (s_evox[j] == v) { first = j; break; }
        s_lead[i] = (first == i) ? 1 : 0;
        atomicAdd(&s_lw[first * 4 + s_eray[i]], s_ew[i]);
    }
    __syncthreads();

    float4 c0 = ((const float4*)s_ctx[0])[lane];
    float4 c1 = ((const float4*)s_ctx[1])[lane];
    float4 c2 = ((const float4*)s_ctx[2])[lane];
    float4 c3 = ((const float4*)s_ctx[3])[lane];
    for (int e = warp; e < N; e += 4) {
        if (!s_lead[e]) continue;
        float a0 = s_lw[e*4], a1 = s_lw[e*4+1], a2 = s_lw[e*4+2], a3 = s_lw[e*4+3];
        float vx = a0*c0.x + a1*c1.x + a2*c2.x + a3*c3.x;
        float vy = a0*c0.y + a1*c1.y + a2*c2.y + a3*c3.y;
        float vz = a0*c0.z + a1*c1.z + a2*c2.z + a3*c3.z;
        float vw = a0*c0.w + a1*c1.w + a2*c2.w + a3*c3.w;
        float* ptr = scratch + (size_t)s_evox[e] * CC + lane * 4;
        asm volatile("red.global.add.v4.f32 [%0], {%1,%2,%3,%4};"
                     :: "l"(ptr), "f"(vx), "f"(vy), "f"(vz), "f"(vw)
                     : "memory");
    }
}

// ---------------- scratch [vz][xy][c] -> out [vz][c][xy] ----------------
__global__ __launch_bounds__(256)
void bev_transpose(const float* __restrict__ scratch, float* __restrict__ out)
{
    __shared__ float s[32][129];
    int vz = blockIdx.y;
    int xy0 = blockIdx.x * 32;
    int tid = threadIdx.x;
    #pragma unroll
    for (int i = 0; i < 16; i++) {
        int idx = tid + i * 256;
        int c = idx & 127, xyl = idx >> 7;
        int xy = xy0 + xyl;
        s[xyl][c] = (xy < NXY) ? scratch[((size_t)vz * NXY + xy) * CC + c] : 0.f;
    }
    __syncthreads();
    #pragma unroll
    for (int i = 0; i < 16; i++) {
        int idx = tid + i * 256;
        int xyl = idx & 31, c = idx >> 5;
        int xy = xy0 + xyl;
        if (xy < NXY) out[((size_t)vz * CC + c) * NXY + xy] = s[xyl][c];
    }
}

// ---------------- launcher ----------------
extern "C" void kernel_launch(void* const* d_in, const int* in_sizes, int n_in,
                              void* d_out, int out_size)
{
    const float* rot    = (const float*)d_in[0];
    const float* ctrans = (const float*)d_in[1];
    const float* intr   = (const float*)d_in[2];
    const float* prot   = (const float*)d_in[3];
    const float* ptrans = (const float*)d_in[4];
    const float* img    = (const float*)d_in[5];
    const float* w1 = (const float*)d_in[6];
    const float* b1 = (const float*)d_in[7];
    const float* g1 = (const float*)d_in[8];
    const float* be1= (const float*)d_in[9];
    const float* m1 = (const float*)d_in[10];
    const float* v1 = (const float*)d_in[11];
    const float* w2 = (const float*)d_in[12];
    const float* b2 = (const float*)d_in[13];
    const float* g2 = (const float*)d_in[14];
    const float* be2= (const float*)d_in[15];
    const float* m2 = (const float*)d_in[16];
    const float* v2 = (const float*)d_in[17];
    const float* w3 = (const float*)d_in[18];
    const float* b3 = (const float*)d_in[19];
    float* out = (float*)d_out;

    __half *actA, *actB, *wp1, *wp2, *wp3;
    float *logits, *ss, *scratch;
    cudaGetSymbolAddress((void**)&actA, g_actA);
    cudaGetSymbolAddress((void**)&actB, g_actB);
    cudaGetSymbolAddress((void**)&wp1, g_wp1);
    cudaGetSymbolAddress((void**)&wp2, g_wp2);
    cudaGetSymbolAddress((void**)&wp3, g_wp3);
    cudaGetSymbolAddress((void**)&logits, g_logits);
    cudaGetSymbolAddress((void**)&ss, g_ss);
    cudaGetSymbolAddress((void**)&scratch, g_scratch);

    cudaFuncSetAttribute(gemm_conv, cudaFuncAttributeMaxDynamicSharedMemorySize, SMEM_TOTAL);

    prep_w3x3<<<(9*4*256*64)/256, 256>>>(w1, wp1);
    prep_w3x3<<<(9*4*256*64)/256, 256>>>(w2, wp2);
    prep_w1x1<<<(4*256*64)/256, 256>>>(w3, wp3);
    dim3 cvgrid((HWPX + 63)/64, FCH/64, NCAM);
    convert_in<<<cvgrid, 256>>>(img, actA);
    prep_ss<<<1, 256>>>(b1,g1,be1,m1,v1, b2,g2,be2,m2,v2, b3);

    gemm_conv<<<NTILES, 512, SMEM_TOTAL>>>(actA, wp1, ss,        ss + 256, actB, nullptr, 9, 0);
    gemm_conv<<<NTILES, 512, SMEM_TOTAL>>>(actB, wp2, ss + 512,  ss + 768, actA, nullptr, 9, 0);
    gemm_conv<<<NTILES, 512, SMEM_TOTAL>>>(actA, wp3, ss + 1024, nullptr,  nullptr, logits, 1, 1);

    prep_mats<<<1, 32>>>(rot, ctrans, intr, prot, ptrans);
    cudaMemsetAsync(scratch, 0, sizeof(float)*(size_t)NZV*NXY*CC, 0);

    scatter_kernel<<<NPX/4, 128>>>(logits, scratch);

    bev_transpose<<<dim3((NXY + 31)/32, NZV), 256>>>(scratch, out);
}